// round 1
// baseline (speedup 1.0000x reference)
#include <cuda_runtime.h>
#include <math.h>

#define Bz 32
#define NFr 16
#define Dd 256
#define Ss 21
#define Nn 192   // H*W = 8*24
#define NA 20
#define EPSs 1e-8f
#define LN_EPS 1e-5f

// ---------------- scratch (device globals; no allocation allowed) ------------
__device__ float g_K[Bz * Nn * Dd];
__device__ float g_V[Bz * Nn * Dd];
__device__ float g_slots[Bz * Ss * Dd];
__device__ float g_Q[Bz * Ss * Dd];
__device__ float g_A[Bz * Ss * Nn];
__device__ float g_upd[Bz * Ss * Dd];
__device__ float g_H[Bz * Ss * Dd];
__device__ float g_FF[Bz * Ss * Dd];

// ---------------- helpers ----------------------------------------------------
__device__ __forceinline__ float block_reduce_sum_256(float v, float* sbuf) {
    int t = threadIdx.x;
    #pragma unroll
    for (int o = 16; o > 0; o >>= 1) v += __shfl_down_sync(0xffffffffu, v, o);
    if ((t & 31) == 0) sbuf[t >> 5] = v;
    __syncthreads();
    if (t == 0) {
        float s = 0.f;
        #pragma unroll
        for (int i = 0; i < 8; i++) s += sbuf[i];
        sbuf[0] = s;
    }
    __syncthreads();
    float r = sbuf[0];
    __syncthreads();
    return r;
}

// ---------------- kernels ----------------------------------------------------

// slots0 = mu + sigma * noise   (B*S*D threads)
__global__ void init_slots_kernel(const float* __restrict__ noise,
                                  const float* __restrict__ mu,
                                  const float* __restrict__ sigma) {
    int idx = blockIdx.x * blockDim.x + threadIdx.x;
    int d = idx & (Dd - 1);
    g_slots[idx] = mu[d] + sigma[d] * noise[idx];
}

// x = LN(frame); K = x@Wk^T+bk; V = x@Wv^T+bv.  grid = B*N blocks, 256 thr.
__global__ void ln_kv_kernel(const float* __restrict__ inputs, int f,
                             const float* __restrict__ gam,
                             const float* __restrict__ bet,
                             const float* __restrict__ Wk, const float* __restrict__ bk,
                             const float* __restrict__ Wv, const float* __restrict__ bv) {
    __shared__ float xs[Dd];
    __shared__ float sbuf[8];
    int row = blockIdx.x;                  // b*Nn + n
    int b = row / Nn, n = row - b * Nn;
    const float* src = inputs + (((size_t)b * NFr + f) * Nn + n) * Dd;
    int t = threadIdx.x;
    float x = src[t];
    float m = block_reduce_sum_256(x, sbuf) * (1.0f / Dd);
    float dv = x - m;
    float var = block_reduce_sum_256(dv * dv, sbuf) * (1.0f / Dd);
    xs[t] = dv * rsqrtf(var + LN_EPS) * gam[t] + bet[t];
    __syncthreads();
    float accK = bk[t], accV = bv[t];
    const float* wkr = Wk + (size_t)t * Dd;
    const float* wvr = Wv + (size_t)t * Dd;
    #pragma unroll 8
    for (int e = 0; e < Dd; e++) {
        float xe = xs[e];
        accK = fmaf(xe, wkr[e], accK);
        accV = fmaf(xe, wvr[e], accV);
    }
    g_K[(size_t)row * Dd + t] = accK;
    g_V[(size_t)row * Dd + t] = accV;
}

// Q = LN(slots)@Wq^T + bq.  grid = B*S blocks.
__global__ void q_kernel(const float* __restrict__ gam, const float* __restrict__ bet,
                         const float* __restrict__ Wq, const float* __restrict__ bq) {
    __shared__ float xs[Dd];
    __shared__ float sbuf[8];
    int row = blockIdx.x;
    int t = threadIdx.x;
    float x = g_slots[(size_t)row * Dd + t];
    float m = block_reduce_sum_256(x, sbuf) * (1.0f / Dd);
    float dv = x - m;
    float var = block_reduce_sum_256(dv * dv, sbuf) * (1.0f / Dd);
    xs[t] = dv * rsqrtf(var + LN_EPS) * gam[t] + bet[t];
    __syncthreads();
    float acc = bq[t];
    const float* wr = Wq + (size_t)t * Dd;
    #pragma unroll 8
    for (int e = 0; e < Dd; e++) acc = fmaf(xs[e], wr[e], acc);
    g_Q[(size_t)row * Dd + t] = acc;
}

// dots[b,i,j] over i; softmax over slot axis i; +EPS.  grid = B*N blocks.
// Optionally writes attn_ori to the output tensor (last iteration of frame).
__global__ void dots_softmax_kernel(int f, int store_out, float* __restrict__ out_attn) {
    __shared__ float ks[Dd];
    __shared__ float dv[Ss];
    int row = blockIdx.x;                 // b*Nn + j
    int b = row / Nn, j = row - b * Nn;
    int t = threadIdx.x, w = t >> 5, l = t & 31;
    ks[t] = g_K[(size_t)row * Dd + t];
    __syncthreads();
    for (int i = w; i < Ss; i += 8) {
        const float* qr = g_Q + ((size_t)b * Ss + i) * Dd;
        float p = 0.f;
        #pragma unroll 2
        for (int e = l; e < Dd; e += 32) p = fmaf(qr[e], ks[e], p);
        #pragma unroll
        for (int o = 16; o > 0; o >>= 1) p += __shfl_down_sync(0xffffffffu, p, o);
        if (l == 0) dv[i] = p * 0.0625f;   // D^-0.5 = 1/16
    }
    __syncthreads();
    if (w == 0) {
        float v = (l < Ss) ? dv[l] : -1e30f;
        float mx = v;
        #pragma unroll
        for (int o = 16; o > 0; o >>= 1) mx = fmaxf(mx, __shfl_xor_sync(0xffffffffu, mx, o));
        float e = (l < Ss) ? expf(v - mx) : 0.f;
        float sm = e;
        #pragma unroll
        for (int o = 16; o > 0; o >>= 1) sm += __shfl_xor_sync(0xffffffffu, sm, o);
        float a = e / sm + EPSs;
        if (l < Ss) {
            g_A[((size_t)b * Ss + l) * Nn + j] = a;
            if (store_out)
                out_attn[(((size_t)b * NFr + f) * Ss + l) * Nn + j] = a;
        }
    }
}

// updates[b,i,d] = sum_j V[b,j,d] * A[b,i,j] / rowsum_j(A).  grid = B*S blocks.
__global__ void updates_kernel() {
    __shared__ float as[Nn];
    __shared__ float sbuf[8];
    int row = blockIdx.x;                 // b*Ss + i
    int b = row / Ss;
    int t = threadIdx.x;
    float av = (t < Nn) ? g_A[(size_t)row * Nn + t] : 0.f;
    if (t < Nn) as[t] = av;
    float rs = block_reduce_sum_256(av, sbuf);   // contains syncthreads -> as[] visible
    float inv = 1.0f / rs;
    const float* vb = g_V + (size_t)b * Nn * Dd;
    float acc = 0.f;
    #pragma unroll 8
    for (int jj = 0; jj < Nn; jj++) acc = fmaf(as[jj], vb[(size_t)jj * Dd + t], acc);
    g_upd[(size_t)row * Dd + t] = acc * inv;
}

// GRUCell: h = (1-z)*n + z*slots.  grid = B*S blocks.
__global__ void gru_kernel(const float* __restrict__ W_ih, const float* __restrict__ b_ih,
                           const float* __restrict__ W_hh, const float* __restrict__ b_hh) {
    __shared__ float us[Dd];
    __shared__ float hs[Dd];
    int row = blockIdx.x;
    int t = threadIdx.x;
    us[t] = g_upd[(size_t)row * Dd + t];
    float hprev = g_slots[(size_t)row * Dd + t];
    hs[t] = hprev;
    __syncthreads();
    float ir = b_ih[t], iz = b_ih[Dd + t], inn = b_ih[2 * Dd + t];
    float hr = b_hh[t], hz = b_hh[Dd + t], hn = b_hh[2 * Dd + t];
    const float* wir = W_ih + (size_t)t * Dd;
    const float* wiz = W_ih + (size_t)(Dd + t) * Dd;
    const float* win = W_ih + (size_t)(2 * Dd + t) * Dd;
    const float* whr = W_hh + (size_t)t * Dd;
    const float* whz = W_hh + (size_t)(Dd + t) * Dd;
    const float* whn = W_hh + (size_t)(2 * Dd + t) * Dd;
    #pragma unroll 4
    for (int e = 0; e < Dd; e++) {
        float u = us[e], h = hs[e];
        ir  = fmaf(u, wir[e], ir);
        iz  = fmaf(u, wiz[e], iz);
        inn = fmaf(u, win[e], inn);
        hr  = fmaf(h, whr[e], hr);
        hz  = fmaf(h, whz[e], hz);
        hn  = fmaf(h, whn[e], hn);
    }
    float r = 1.f / (1.f + expf(-(ir + hr)));
    float z = 1.f / (1.f + expf(-(iz + hz)));
    float n = tanhf(inn + r * hn);
    g_H[(size_t)row * Dd + t] = (1.f - z) * n + z * hprev;
}

// FF = relu(LN(h)@W1^T + b1).  grid = B*S blocks.
__global__ void ff_kernel(const float* __restrict__ gam, const float* __restrict__ bet,
                          const float* __restrict__ W1, const float* __restrict__ b1) {
    __shared__ float xs[Dd];
    __shared__ float sbuf[8];
    int row = blockIdx.x;
    int t = threadIdx.x;
    float x = g_H[(size_t)row * Dd + t];
    float m = block_reduce_sum_256(x, sbuf) * (1.0f / Dd);
    float dv = x - m;
    float var = block_reduce_sum_256(dv * dv, sbuf) * (1.0f / Dd);
    xs[t] = dv * rsqrtf(var + LN_EPS) * gam[t] + bet[t];
    __syncthreads();
    float acc = b1[t];
    const float* wr = W1 + (size_t)t * Dd;
    #pragma unroll 8
    for (int e = 0; e < Dd; e++) acc = fmaf(xs[e], wr[e], acc);
    g_FF[(size_t)row * Dd + t] = fmaxf(acc, 0.f);
}

// slots = h + FF@W2^T + b2.  grid = B*S blocks.
__global__ void mlp2_kernel(const float* __restrict__ W2, const float* __restrict__ b2) {
    __shared__ float fs[Dd];
    int row = blockIdx.x;
    int t = threadIdx.x;
    fs[t] = g_FF[(size_t)row * Dd + t];
    __syncthreads();
    float acc = b2[t];
    const float* wr = W2 + (size_t)t * Dd;
    #pragma unroll 8
    for (int e = 0; e < Dd; e++) acc = fmaf(fs[e], wr[e], acc);
    g_slots[(size_t)row * Dd + t] = g_H[(size_t)row * Dd + t] + acc;
}

// slots_out = slots[:, :NA, :]
__global__ void out_slots_kernel(float* __restrict__ out) {
    int idx = blockIdx.x * blockDim.x + threadIdx.x;  // B*NA*D
    int d = idx & (Dd - 1);
    int rest = idx / Dd;
    int s = rest % NA;
    int b = rest / NA;
    out[idx] = g_slots[((size_t)b * Ss + s) * Dd + d];
}

// ---------------- launch ------------------------------------------------------
extern "C" void kernel_launch(void* const* d_in, const int* in_sizes, int n_in,
                              void* d_out, int out_size) {
    const float* inputs  = (const float*)d_in[0];
    const float* noise   = (const float*)d_in[1];
    const float* mu      = (const float*)d_in[2];
    const float* sigma   = (const float*)d_in[3];
    const float* Wq      = (const float*)d_in[4];
    const float* bq      = (const float*)d_in[5];
    const float* Wk      = (const float*)d_in[6];
    const float* bk      = (const float*)d_in[7];
    const float* Wv      = (const float*)d_in[8];
    const float* bv      = (const float*)d_in[9];
    const float* W1      = (const float*)d_in[10];
    const float* b1      = (const float*)d_in[11];
    const float* W2      = (const float*)d_in[12];
    const float* b2      = (const float*)d_in[13];
    const float* W_ih    = (const float*)d_in[14];
    const float* b_ih    = (const float*)d_in[15];
    const float* W_hh    = (const float*)d_in[16];
    const float* b_hh    = (const float*)d_in[17];
    const float* g_in    = (const float*)d_in[18];
    const float* be_in   = (const float*)d_in[19];
    const float* g_sl    = (const float*)d_in[20];
    const float* be_sl   = (const float*)d_in[21];
    const float* g_ff    = (const float*)d_in[22];
    const float* be_ff   = (const float*)d_in[23];

    float* out = (float*)d_out;
    float* out_attn = out + (size_t)Bz * NA * Dd;   // attns after slots_out

    init_slots_kernel<<<(Bz * Ss * Dd) / 256, 256>>>(noise, mu, sigma);

    for (int f = 0; f < NFr; f++) {
        ln_kv_kernel<<<Bz * Nn, 256>>>(inputs, f, g_in, be_in, Wk, bk, Wv, bv);
        for (int it = 0; it < 3; it++) {
            q_kernel<<<Bz * Ss, 256>>>(g_sl, be_sl, Wq, bq);
            dots_softmax_kernel<<<Bz * Nn, 256>>>(f, (it == 2) ? 1 : 0, out_attn);
            updates_kernel<<<Bz * Ss, 256>>>();
            gru_kernel<<<Bz * Ss, 256>>>(W_ih, b_ih, W_hh, b_hh);
            ff_kernel<<<Bz * Ss, 256>>>(g_ff, be_ff, W1, b1);
            mlp2_kernel<<<Bz * Ss, 256>>>(W2, b2);
        }
    }

    out_slots_kernel<<<(Bz * NA * Dd) / 256, 256>>>(out);
}

// round 2
// speedup vs baseline: 16.6133x; 16.6133x over previous
#include <cuda_runtime.h>
#include <math.h>

#define Bz 32
#define NFr 16
#define Dd 256
#define Ss 21
#define Nn 192
#define NA 20
#define EPSs 1e-8f
#define LN_EPS 1e-5f
#define RLN 16   // rows per block in ln_kv
#define RQ 8     // rows per block in q_kernel
#define RS 7     // slot rows per block in slot_update

// ---------------- scratch ----------------------------------------------------
__device__ float g_K[Bz * Nn * Dd];
__device__ float g_V[Bz * Nn * Dd];
__device__ float g_slots[Bz * Ss * Dd];
__device__ float g_Q[Bz * Ss * Dd];
__device__ float g_At[Bz * Nn * Ss];       // attn_ori transposed: [b][j][i]
__device__ float g_WqT[Dd * Dd];
__device__ float g_WkT[Dd * Dd];
__device__ float g_WvT[Dd * Dd];
__device__ float g_W1T[Dd * Dd];
__device__ float g_W2T[Dd * Dd];
__device__ float g_WihT[Dd * 3 * Dd];      // [k][g], g<768
__device__ float g_WhhT[Dd * 3 * Dd];

// ---------------- transpose: dst[c][r] = src[r][c] ---------------------------
__global__ void transpose_kernel(const float* __restrict__ src, float* __restrict__ dst,
                                 int rows, int cols) {
    __shared__ float tile[32][33];
    int bx = blockIdx.x * 32, by = blockIdx.y * 32;
    int tx = threadIdx.x, ty = threadIdx.y;
    int x = bx + tx;
    #pragma unroll
    for (int i = 0; i < 32; i += 8) {
        int y = by + ty + i;
        if (y < rows && x < cols) tile[ty + i][tx] = src[(size_t)y * cols + x];
    }
    __syncthreads();
    int x2 = by + tx;
    #pragma unroll
    for (int i = 0; i < 32; i += 8) {
        int y2 = bx + ty + i;
        if (y2 < cols && x2 < rows) dst[(size_t)y2 * rows + x2] = tile[tx][ty + i];
    }
}

// ---------------- init slots --------------------------------------------------
__global__ void init_slots_kernel(const float* __restrict__ noise,
                                  const float* __restrict__ mu,
                                  const float* __restrict__ sigma) {
    int idx = blockIdx.x * blockDim.x + threadIdx.x;
    int d = idx & (Dd - 1);
    g_slots[idx] = mu[d] + sigma[d] * noise[idx];
}

// ---------------- warp helpers ------------------------------------------------
__device__ __forceinline__ float warp_sum(float v) {
    #pragma unroll
    for (int o = 16; o > 0; o >>= 1) v += __shfl_xor_sync(0xffffffffu, v, o);
    return v;
}
__device__ __forceinline__ float warp_max(float v) {
    #pragma unroll
    for (int o = 16; o > 0; o >>= 1) v = fmaxf(v, __shfl_xor_sync(0xffffffffu, v, o));
    return v;
}

// ---------------- LN(frame) -> K,V.  grid = B*N/RLN, 256 thr -----------------
__global__ __launch_bounds__(256)
void ln_kv_kernel(const float* __restrict__ inputs, int f,
                  const float* __restrict__ gam, const float* __restrict__ bet,
                  const float* __restrict__ bk, const float* __restrict__ bv) {
    __shared__ float xs[RLN][Dd];
    int row0 = blockIdx.x * RLN;
    int t = threadIdx.x, w = t >> 5, l = t & 31;

    // LN: each warp normalizes 2 rows
    for (int rr = w; rr < RLN; rr += 8) {
        int row = row0 + rr;
        int b = row / Nn, n = row - b * Nn;
        const float* src = inputs + (((size_t)b * NFr + f) * Nn + n) * Dd;
        float v[8]; float s = 0.f;
        #pragma unroll
        for (int u = 0; u < 8; u++) { v[u] = src[l + 32 * u]; s += v[u]; }
        s = warp_sum(s);
        float m = s * (1.0f / Dd);
        float vs = 0.f;
        #pragma unroll
        for (int u = 0; u < 8; u++) { v[u] -= m; vs += v[u] * v[u]; }
        vs = warp_sum(vs);
        float inv = rsqrtf(vs * (1.0f / Dd) + LN_EPS);
        #pragma unroll
        for (int u = 0; u < 8; u++) {
            int k = l + 32 * u;
            xs[rr][k] = v[u] * inv * gam[k] + bet[k];
        }
    }
    __syncthreads();

    int c = t;
    float aK[RLN], aV[RLN];
    float bkc = bk[c], bvc = bv[c];
    #pragma unroll
    for (int r = 0; r < RLN; r++) { aK[r] = bkc; aV[r] = bvc; }
    const float* wkp = g_WkT + c;
    const float* wvp = g_WvT + c;
    for (int k = 0; k < Dd; k += 4) {
        float wk0 = wkp[(k + 0) * Dd], wk1 = wkp[(k + 1) * Dd];
        float wk2 = wkp[(k + 2) * Dd], wk3 = wkp[(k + 3) * Dd];
        float wv0 = wvp[(k + 0) * Dd], wv1 = wvp[(k + 1) * Dd];
        float wv2 = wvp[(k + 2) * Dd], wv3 = wvp[(k + 3) * Dd];
        #pragma unroll
        for (int r = 0; r < RLN; r++) {
            float4 x4 = *(const float4*)&xs[r][k];
            aK[r] = fmaf(x4.x, wk0, aK[r]); aK[r] = fmaf(x4.y, wk1, aK[r]);
            aK[r] = fmaf(x4.z, wk2, aK[r]); aK[r] = fmaf(x4.w, wk3, aK[r]);
            aV[r] = fmaf(x4.x, wv0, aV[r]); aV[r] = fmaf(x4.y, wv1, aV[r]);
            aV[r] = fmaf(x4.z, wv2, aV[r]); aV[r] = fmaf(x4.w, wv3, aV[r]);
        }
    }
    #pragma unroll
    for (int r = 0; r < RLN; r++) {
        g_K[(size_t)(row0 + r) * Dd + c] = aK[r];
        g_V[(size_t)(row0 + r) * Dd + c] = aV[r];
    }
}

// ---------------- Q = LN(slots)@WqT + bq.  grid = 672/RQ ----------------------
__global__ __launch_bounds__(256)
void q_kernel(const float* __restrict__ gam, const float* __restrict__ bet,
              const float* __restrict__ bq) {
    __shared__ float xs[RQ][Dd];
    int row0 = blockIdx.x * RQ;
    int t = threadIdx.x, w = t >> 5, l = t & 31;
    if (w < RQ) {
        int row = row0 + w;
        const float* src = g_slots + (size_t)row * Dd;
        float v[8]; float s = 0.f;
        #pragma unroll
        for (int u = 0; u < 8; u++) { v[u] = src[l + 32 * u]; s += v[u]; }
        s = warp_sum(s);
        float m = s * (1.0f / Dd);
        float vs = 0.f;
        #pragma unroll
        for (int u = 0; u < 8; u++) { v[u] -= m; vs += v[u] * v[u]; }
        vs = warp_sum(vs);
        float inv = rsqrtf(vs * (1.0f / Dd) + LN_EPS);
        #pragma unroll
        for (int u = 0; u < 8; u++) {
            int k = l + 32 * u;
            xs[w][k] = v[u] * inv * gam[k] + bet[k];
        }
    }
    __syncthreads();
    int c = t;
    float acc[RQ];
    float bqc = bq[c];
    #pragma unroll
    for (int r = 0; r < RQ; r++) acc[r] = bqc;
    const float* wp = g_WqT + c;
    for (int k = 0; k < Dd; k += 4) {
        float w0 = wp[(k + 0) * Dd], w1 = wp[(k + 1) * Dd];
        float w2 = wp[(k + 2) * Dd], w3 = wp[(k + 3) * Dd];
        #pragma unroll
        for (int r = 0; r < RQ; r++) {
            float4 x4 = *(const float4*)&xs[r][k];
            acc[r] = fmaf(x4.x, w0, acc[r]); acc[r] = fmaf(x4.y, w1, acc[r]);
            acc[r] = fmaf(x4.z, w2, acc[r]); acc[r] = fmaf(x4.w, w3, acc[r]);
        }
    }
    #pragma unroll
    for (int r = 0; r < RQ; r++) g_Q[(size_t)(row0 + r) * Dd + c] = acc[r];
}

// ---------------- dots + softmax(+eps).  grid = B * (N/32) --------------------
__global__ __launch_bounds__(256)
void dots_softmax_kernel(int f, int store_out, float* __restrict__ out_attn) {
    __shared__ float Ks[32][65];
    __shared__ float Qs[Ss][64];
    __shared__ float ds[32][24];
    int b = blockIdx.x / (Nn / 32);
    int j0 = (blockIdx.x % (Nn / 32)) * 32;
    int t = threadIdx.x, w = t >> 5, l = t & 31;
    int jj = l, y = w;
    int i0 = y, i1 = y + 8, i2 = y + 16;
    bool has2 = (i2 < Ss);
    float a0 = 0.f, a1 = 0.f, a2 = 0.f;

    for (int k0 = 0; k0 < Dd; k0 += 64) {
        for (int idx = t; idx < 32 * 64; idx += 256) {
            int r = idx >> 6, kk = idx & 63;
            Ks[r][kk] = g_K[((size_t)b * Nn + j0 + r) * Dd + k0 + kk];
        }
        for (int idx = t; idx < Ss * 64; idx += 256) {
            int r = idx >> 6, kk = idx & 63;
            Qs[r][kk] = g_Q[((size_t)b * Ss + r) * Dd + k0 + kk];
        }
        __syncthreads();
        #pragma unroll
        for (int kk = 0; kk < 64; kk += 4) {
            float kv0 = Ks[jj][kk + 0], kv1 = Ks[jj][kk + 1];
            float kv2 = Ks[jj][kk + 2], kv3 = Ks[jj][kk + 3];
            float4 q0 = *(const float4*)&Qs[i0][kk];
            float4 q1 = *(const float4*)&Qs[i1][kk];
            a0 = fmaf(kv0, q0.x, a0); a0 = fmaf(kv1, q0.y, a0);
            a0 = fmaf(kv2, q0.z, a0); a0 = fmaf(kv3, q0.w, a0);
            a1 = fmaf(kv0, q1.x, a1); a1 = fmaf(kv1, q1.y, a1);
            a1 = fmaf(kv2, q1.z, a1); a1 = fmaf(kv3, q1.w, a1);
            if (has2) {
                float4 q2 = *(const float4*)&Qs[i2][kk];
                a2 = fmaf(kv0, q2.x, a2); a2 = fmaf(kv1, q2.y, a2);
                a2 = fmaf(kv2, q2.z, a2); a2 = fmaf(kv3, q2.w, a2);
            }
        }
        __syncthreads();
    }
    ds[jj][i0] = a0 * 0.0625f;
    ds[jj][i1] = a1 * 0.0625f;
    if (has2) ds[jj][i2] = a2 * 0.0625f;
    __syncthreads();

    // softmax over slot axis per column j
    for (int q = w; q < 32; q += 8) {
        float v = (l < Ss) ? ds[q][l] : -3.4e38f;
        float mx = warp_max(v);
        float e = (l < Ss) ? expf(v - mx) : 0.f;
        float sm = warp_sum(e);
        if (l < Ss) {
            float a = e / sm + EPSs;
            g_At[((size_t)b * Nn + j0 + q) * Ss + l] = a;
            if (store_out)
                out_attn[(((size_t)b * NFr + f) * Ss + l) * Nn + j0 + q] = a;
        }
    }
}

// ------- fused: updates + GRU + LN + FF + mlp2 + next-iter Q ------------------
// grid = B * (S/RS) = 96 blocks, 256 threads
__global__ __launch_bounds__(256)
void slot_update_kernel(const float* __restrict__ b_ih, const float* __restrict__ b_hh,
                        const float* __restrict__ g_ff, const float* __restrict__ be_ff,
                        const float* __restrict__ b1, const float* __restrict__ b2,
                        const float* __restrict__ g_sl, const float* __restrict__ be_sl,
                        const float* __restrict__ bq) {
    __shared__ float as_[RS][Nn];
    __shared__ float us[RS][Dd];
    __shared__ float hs[RS][Dd];
    __shared__ float fs[RS][Dd];
    __shared__ float inv_[RS];

    int b = blockIdx.x / 3;
    int i0 = (blockIdx.x % 3) * RS;
    int t = threadIdx.x, w = t >> 5, l = t & 31;
    int c = t;

    // Phase A: stage attn rows + row sums
    for (int idx = t; idx < RS * Nn; idx += 256) {
        int j = idx / RS, r = idx - j * RS;
        as_[r][j] = g_At[((size_t)b * Nn + j) * Ss + i0 + r];
    }
    __syncthreads();
    if (w < RS) {
        float s = 0.f;
        #pragma unroll
        for (int u = 0; u < Nn / 32; u++) s += as_[w][l + 32 * u];
        s = warp_sum(s);
        if (l == 0) inv_[w] = 1.0f / s;
    }
    // Phase B: updates = (A/rowsum) @ V   (thread owns col c, RS rows)
    float h0[RS];
    #pragma unroll
    for (int r = 0; r < RS; r++)
        h0[r] = g_slots[((size_t)b * Ss + i0 + r) * Dd + c];
    float acc[RS];
    #pragma unroll
    for (int r = 0; r < RS; r++) acc[r] = 0.f;
    __syncthreads();
    const float* vp = g_V + (size_t)b * Nn * Dd + c;
    for (int j = 0; j < Nn; j += 4) {
        float v0 = vp[(j + 0) * Dd], v1 = vp[(j + 1) * Dd];
        float v2 = vp[(j + 2) * Dd], v3 = vp[(j + 3) * Dd];
        #pragma unroll
        for (int r = 0; r < RS; r++) {
            float4 a4 = *(const float4*)&as_[r][j];
            acc[r] = fmaf(a4.x, v0, acc[r]); acc[r] = fmaf(a4.y, v1, acc[r]);
            acc[r] = fmaf(a4.z, v2, acc[r]); acc[r] = fmaf(a4.w, v3, acc[r]);
        }
    }
    #pragma unroll
    for (int r = 0; r < RS; r++) {
        us[r][c] = acc[r] * inv_[r];
        hs[r][c] = h0[r];
    }
    __syncthreads();

    // Phase C: GRU gates
    float ir[RS], iz[RS], in_[RS], hr[RS], hz[RS], hn[RS];
    {
        float bir = b_ih[c], biz = b_ih[Dd + c], bin = b_ih[2 * Dd + c];
        float bhr = b_hh[c], bhz = b_hh[Dd + c], bhn = b_hh[2 * Dd + c];
        #pragma unroll
        for (int r = 0; r < RS; r++) {
            ir[r] = bir; iz[r] = biz; in_[r] = bin;
            hr[r] = bhr; hz[r] = bhz; hn[r] = bhn;
        }
    }
    const float* wip = g_WihT + c;
    const float* whp = g_WhhT + c;
    for (int k = 0; k < Dd; k += 2) {
        float wir0 = wip[(k + 0) * 3 * Dd], wir1 = wip[(k + 1) * 3 * Dd];
        float wiz0 = wip[(k + 0) * 3 * Dd + Dd], wiz1 = wip[(k + 1) * 3 * Dd + Dd];
        float win0 = wip[(k + 0) * 3 * Dd + 2 * Dd], win1 = wip[(k + 1) * 3 * Dd + 2 * Dd];
        float whr0 = whp[(k + 0) * 3 * Dd], whr1 = whp[(k + 1) * 3 * Dd];
        float whz0 = whp[(k + 0) * 3 * Dd + Dd], whz1 = whp[(k + 1) * 3 * Dd + Dd];
        float whn0 = whp[(k + 0) * 3 * Dd + 2 * Dd], whn1 = whp[(k + 1) * 3 * Dd + 2 * Dd];
        #pragma unroll
        for (int r = 0; r < RS; r++) {
            float2 u2 = *(const float2*)&us[r][k];
            float2 h2 = *(const float2*)&hs[r][k];
            ir[r]  = fmaf(u2.x, wir0, ir[r]);  ir[r]  = fmaf(u2.y, wir1, ir[r]);
            iz[r]  = fmaf(u2.x, wiz0, iz[r]);  iz[r]  = fmaf(u2.y, wiz1, iz[r]);
            in_[r] = fmaf(u2.x, win0, in_[r]); in_[r] = fmaf(u2.y, win1, in_[r]);
            hr[r]  = fmaf(h2.x, whr0, hr[r]);  hr[r]  = fmaf(h2.y, whr1, hr[r]);
            hz[r]  = fmaf(h2.x, whz0, hz[r]);  hz[r]  = fmaf(h2.y, whz1, hz[r]);
            hn[r]  = fmaf(h2.x, whn0, hn[r]);  hn[r]  = fmaf(h2.y, whn1, hn[r]);
        }
    }
    float hnew[RS];
    #pragma unroll
    for (int r = 0; r < RS; r++) {
        float rg = 1.f / (1.f + expf(-(ir[r] + hr[r])));
        float zg = 1.f / (1.f + expf(-(iz[r] + hz[r])));
        float ng = tanhf(in_[r] + rg * hn[r]);
        hnew[r] = (1.f - zg) * ng + zg * h0[r];
    }
    __syncthreads();           // everyone done reading us/hs
    #pragma unroll
    for (int r = 0; r < RS; r++) us[r][c] = hnew[r];
    __syncthreads();

    // Phase D: LN(hnew) with g_ff -> hs
    if (w < RS) {
        float v[8]; float s = 0.f;
        #pragma unroll
        for (int u = 0; u < 8; u++) { v[u] = us[w][l + 32 * u]; s += v[u]; }
        s = warp_sum(s);
        float m = s * (1.0f / Dd);
        float vs = 0.f;
        #pragma unroll
        for (int u = 0; u < 8; u++) { v[u] -= m; vs += v[u] * v[u]; }
        vs = warp_sum(vs);
        float iv = rsqrtf(vs * (1.0f / Dd) + LN_EPS);
        #pragma unroll
        for (int u = 0; u < 8; u++) {
            int k = l + 32 * u;
            hs[w][k] = v[u] * iv * g_ff[k] + be_ff[k];
        }
    }
    __syncthreads();

    // Phase E: FF = relu(hs @ W1T + b1) -> fs
    {
        float a2[RS];
        float b1c = b1[c];
        #pragma unroll
        for (int r = 0; r < RS; r++) a2[r] = b1c;
        const float* wp = g_W1T + c;
        for (int k = 0; k < Dd; k += 4) {
            float w0 = wp[(k + 0) * Dd], w1 = wp[(k + 1) * Dd];
            float w2 = wp[(k + 2) * Dd], w3 = wp[(k + 3) * Dd];
            #pragma unroll
            for (int r = 0; r < RS; r++) {
                float4 x4 = *(const float4*)&hs[r][k];
                a2[r] = fmaf(x4.x, w0, a2[r]); a2[r] = fmaf(x4.y, w1, a2[r]);
                a2[r] = fmaf(x4.z, w2, a2[r]); a2[r] = fmaf(x4.w, w3, a2[r]);
            }
        }
        __syncthreads();       // hs reads done before fs (no hazard) + us reads done
        #pragma unroll
        for (int r = 0; r < RS; r++) fs[r][c] = fmaxf(a2[r], 0.f);
    }
    __syncthreads();

    // Phase F: slots_new = hnew + fs @ W2T + b2 -> global + hs (for Q)
    {
        float a3[RS];
        float b2c = b2[c];
        #pragma unroll
        for (int r = 0; r < RS; r++) a3[r] = b2c;
        const float* wp = g_W2T + c;
        for (int k = 0; k < Dd; k += 4) {
            float w0 = wp[(k + 0) * Dd], w1 = wp[(k + 1) * Dd];
            float w2 = wp[(k + 2) * Dd], w3 = wp[(k + 3) * Dd];
            #pragma unroll
            for (int r = 0; r < RS; r++) {
                float4 x4 = *(const float4*)&fs[r][k];
                a3[r] = fmaf(x4.x, w0, a3[r]); a3[r] = fmaf(x4.y, w1, a3[r]);
                a3[r] = fmaf(x4.z, w2, a3[r]); a3[r] = fmaf(x4.w, w3, a3[r]);
            }
        }
        __syncthreads();
        #pragma unroll
        for (int r = 0; r < RS; r++) {
            float sn = hnew[r] + a3[r];
            g_slots[((size_t)b * Ss + i0 + r) * Dd + c] = sn;
            hs[r][c] = sn;
        }
    }
    __syncthreads();

    // Phase G: next-iteration Q = LN(slots_new; g_sl) @ WqT + bq
    if (w < RS) {
        float v[8]; float s = 0.f;
        #pragma unroll
        for (int u = 0; u < 8; u++) { v[u] = hs[w][l + 32 * u]; s += v[u]; }
        s = warp_sum(s);
        float m = s * (1.0f / Dd);
        float vs = 0.f;
        #pragma unroll
        for (int u = 0; u < 8; u++) { v[u] -= m; vs += v[u] * v[u]; }
        vs = warp_sum(vs);
        float iv = rsqrtf(vs * (1.0f / Dd) + LN_EPS);
        #pragma unroll
        for (int u = 0; u < 8; u++) {
            int k = l + 32 * u;
            fs[w][k] = v[u] * iv * g_sl[k] + be_sl[k];
        }
    }
    __syncthreads();
    {
        float aq[RS];
        float bqc = bq[c];
        #pragma unroll
        for (int r = 0; r < RS; r++) aq[r] = bqc;
        const float* wp = g_WqT + c;
        for (int k = 0; k < Dd; k += 4) {
            float w0 = wp[(k + 0) * Dd], w1 = wp[(k + 1) * Dd];
            float w2 = wp[(k + 2) * Dd], w3 = wp[(k + 3) * Dd];
            #pragma unroll
            for (int r = 0; r < RS; r++) {
                float4 x4 = *(const float4*)&fs[r][k];
                aq[r] = fmaf(x4.x, w0, aq[r]); aq[r] = fmaf(x4.y, w1, aq[r]);
                aq[r] = fmaf(x4.z, w2, aq[r]); aq[r] = fmaf(x4.w, w3, aq[r]);
            }
        }
        #pragma unroll
        for (int r = 0; r < RS; r++)
            g_Q[((size_t)b * Ss + i0 + r) * Dd + c] = aq[r];
    }
}

// ---------------- output slots ------------------------------------------------
__global__ void out_slots_kernel(float* __restrict__ out) {
    int idx = blockIdx.x * blockDim.x + threadIdx.x;
    int d = idx & (Dd - 1);
    int rest = idx / Dd;
    int s = rest % NA;
    int b = rest / NA;
    out[idx] = g_slots[((size_t)b * Ss + s) * Dd + d];
}

// ---------------- launch ------------------------------------------------------
extern "C" void kernel_launch(void* const* d_in, const int* in_sizes, int n_in,
                              void* d_out, int out_size) {
    const float* inputs = (const float*)d_in[0];
    const float* noise  = (const float*)d_in[1];
    const float* mu     = (const float*)d_in[2];
    const float* sigma  = (const float*)d_in[3];
    const float* Wq     = (const float*)d_in[4];
    const float* bq     = (const float*)d_in[5];
    const float* Wk     = (const float*)d_in[6];
    const float* bk     = (const float*)d_in[7];
    const float* Wv     = (const float*)d_in[8];
    const float* bv     = (const float*)d_in[9];
    const float* W1     = (const float*)d_in[10];
    const float* b1     = (const float*)d_in[11];
    const float* W2     = (const float*)d_in[12];
    const float* b2     = (const float*)d_in[13];
    const float* W_ih   = (const float*)d_in[14];
    const float* b_ih   = (const float*)d_in[15];
    const float* W_hh   = (const float*)d_in[16];
    const float* b_hh   = (const float*)d_in[17];
    const float* gin    = (const float*)d_in[18];
    const float* bein   = (const float*)d_in[19];
    const float* gsl    = (const float*)d_in[20];
    const float* besl   = (const float*)d_in[21];
    const float* gff    = (const float*)d_in[22];
    const float* beff   = (const float*)d_in[23];

    float* out = (float*)d_out;
    float* out_attn = out + (size_t)Bz * NA * Dd;

    float *dWqT, *dWkT, *dWvT, *dW1T, *dW2T, *dWihT, *dWhhT;
    cudaGetSymbolAddress((void**)&dWqT, g_WqT);
    cudaGetSymbolAddress((void**)&dWkT, g_WkT);
    cudaGetSymbolAddress((void**)&dWvT, g_WvT);
    cudaGetSymbolAddress((void**)&dW1T, g_W1T);
    cudaGetSymbolAddress((void**)&dW2T, g_W2T);
    cudaGetSymbolAddress((void**)&dWihT, g_WihT);
    cudaGetSymbolAddress((void**)&dWhhT, g_WhhT);

    dim3 tb(32, 8);
    transpose_kernel<<<dim3(8, 8), tb>>>(Wq, dWqT, Dd, Dd);
    transpose_kernel<<<dim3(8, 8), tb>>>(Wk, dWkT, Dd, Dd);
    transpose_kernel<<<dim3(8, 8), tb>>>(Wv, dWvT, Dd, Dd);
    transpose_kernel<<<dim3(8, 8), tb>>>(W1, dW1T, Dd, Dd);
    transpose_kernel<<<dim3(8, 8), tb>>>(W2, dW2T, Dd, Dd);
    transpose_kernel<<<dim3(8, 24), tb>>>(W_ih, dWihT, 3 * Dd, Dd);
    transpose_kernel<<<dim3(8, 24), tb>>>(W_hh, dWhhT, 3 * Dd, Dd);

    init_slots_kernel<<<(Bz * Ss * Dd) / 256, 256>>>(noise, mu, sigma);
    q_kernel<<<(Bz * Ss) / RQ, 256>>>(gsl, besl, bq);

    for (int f = 0; f < NFr; f++) {
        ln_kv_kernel<<<(Bz * Nn) / RLN, 256>>>(inputs, f, gin, bein, bk, bv);
        for (int it = 0; it < 3; it++) {
            dots_softmax_kernel<<<Bz * (Nn / 32), 256>>>(f, (it == 2) ? 1 : 0, out_attn);
            slot_update_kernel<<<Bz * (Ss / RS), 256>>>(b_ih, b_hh, gff, beff,
                                                        b1, b2, gsl, besl, bq);
        }
    }

    out_slots_kernel<<<(Bz * NA * Dd) / 256, 256>>>(out);
}

// round 3
// speedup vs baseline: 22.1687x; 1.3344x over previous
#include <cuda_runtime.h>
#include <math.h>

#define Bz 32
#define NFr 16
#define Dd 256
#define Ss 21
#define Nn 192
#define NA 20
#define EPSs 1e-8f
#define LN_EPS 1e-5f
#define RLN 16   // rows per block in ln_kv (8 pairs)
#define RQ 8     // rows per block in q_kernel
#define RS 7     // slot rows per block in slot_update (4 pairs, last hi = dup)

typedef unsigned long long u64;

// ---------------- packed f32x2 helpers ---------------------------------------
__device__ __forceinline__ void fma2(u64& d, u64 a, u64 b) {
    asm("fma.rn.f32x2 %0, %1, %2, %0;" : "+l"(d) : "l"(a), "l"(b));
}
__device__ __forceinline__ u64 dup2(float v) {
    u64 r; asm("mov.b64 %0, {%1, %1};" : "=l"(r) : "f"(v)); return r;
}
__device__ __forceinline__ float2 unpk(u64 v) {
    float lo, hi; asm("mov.b64 {%0, %1}, %2;" : "=f"(lo), "=f"(hi) : "l"(v));
    return make_float2(lo, hi);
}

// ---------------- scratch ----------------------------------------------------
__device__ float g_K[Bz * Nn * Dd];
__device__ float g_V[Bz * Nn * Dd];
__device__ float g_slots[Bz * Ss * Dd];
__device__ float g_Q[Bz * Ss * Dd];
__device__ float g_At[Bz * Nn * Ss];       // attn_ori transposed: [b][j][i]
__device__ float g_WqT[Dd * Dd];
__device__ float g_WkT[Dd * Dd];
__device__ float g_WvT[Dd * Dd];
__device__ float g_W1T[Dd * Dd];
__device__ float g_W2T[Dd * Dd];
__device__ float g_WihT[Dd * 3 * Dd];      // [k][g]
__device__ float g_WhhT[Dd * 3 * Dd];

// ---------------- fused transpose of all 7 weight matrices -------------------
// mats 0-4: 256x256 (64 tiles each); mats 5-6: 768x256 (192 tiles each)
__global__ void transpose_all_kernel(const float* __restrict__ Wq, const float* __restrict__ Wk,
                                     const float* __restrict__ Wv, const float* __restrict__ W1,
                                     const float* __restrict__ W2, const float* __restrict__ Wih,
                                     const float* __restrict__ Whh) {
    __shared__ float tile[32][33];
    int bid = blockIdx.x;
    const float* src; float* dst; int rows; int tloc; int m;
    if (bid < 320) { m = bid >> 6; tloc = bid & 63; rows = 256; }
    else { m = 5 + (bid - 320) / 192; tloc = (bid - 320) % 192; rows = 768; }
    switch (m) {
        case 0: src = Wq;  dst = g_WqT;  break;
        case 1: src = Wk;  dst = g_WkT;  break;
        case 2: src = Wv;  dst = g_WvT;  break;
        case 3: src = W1;  dst = g_W1T;  break;
        case 4: src = W2;  dst = g_W2T;  break;
        case 5: src = Wih; dst = g_WihT; break;
        default: src = Whh; dst = g_WhhT; break;
    }
    int cols = 256;
    int bx = (tloc & 7) * 32;       // col tile
    int by = (tloc >> 3) * 32;      // row tile
    int tx = threadIdx.x, ty = threadIdx.y;
    int x = bx + tx;
    #pragma unroll
    for (int i = 0; i < 32; i += 8) {
        int y = by + ty + i;
        tile[ty + i][tx] = src[(size_t)y * cols + x];
    }
    __syncthreads();
    int x2 = by + tx;
    #pragma unroll
    for (int i = 0; i < 32; i += 8) {
        int y2 = bx + ty + i;
        dst[(size_t)y2 * rows + x2] = tile[tx][ty + i];
    }
}

// ---------------- init slots --------------------------------------------------
__global__ void init_slots_kernel(const float* __restrict__ noise,
                                  const float* __restrict__ mu,
                                  const float* __restrict__ sigma) {
    int idx = blockIdx.x * blockDim.x + threadIdx.x;
    int d = idx & (Dd - 1);
    g_slots[idx] = mu[d] + sigma[d] * noise[idx];
}

// ---------------- warp helpers ------------------------------------------------
__device__ __forceinline__ float warp_sum(float v) {
    #pragma unroll
    for (int o = 16; o > 0; o >>= 1) v += __shfl_xor_sync(0xffffffffu, v, o);
    return v;
}
__device__ __forceinline__ float warp_max(float v) {
    #pragma unroll
    for (int o = 16; o > 0; o >>= 1) v = fmaxf(v, __shfl_xor_sync(0xffffffffu, v, o));
    return v;
}

// ---------------- LN(frame) -> K,V.  grid = B*N/RLN, 256 thr -----------------
__global__ __launch_bounds__(256)
void ln_kv_kernel(const float* __restrict__ inputs, int f,
                  const float* __restrict__ gam, const float* __restrict__ bet,
                  const float* __restrict__ bk, const float* __restrict__ bv) {
    __shared__ float2 xs2[RLN / 2][Dd];   // pair p = rows (2p, 2p+1)
    int row0 = blockIdx.x * RLN;
    int t = threadIdx.x, w = t >> 5, l = t & 31;

    // LN: each warp normalizes 2 rows (w, w+8), stored into pair-interleaved smem
    for (int rr = w; rr < RLN; rr += 8) {
        int row = row0 + rr;
        int b = row / Nn, n = row - b * Nn;
        const float* src = inputs + (((size_t)b * NFr + f) * Nn + n) * Dd;
        float v[8]; float s = 0.f;
        #pragma unroll
        for (int u = 0; u < 8; u++) { v[u] = src[l + 32 * u]; s += v[u]; }
        s = warp_sum(s);
        float m = s * (1.0f / Dd);
        float vs = 0.f;
        #pragma unroll
        for (int u = 0; u < 8; u++) { v[u] -= m; vs += v[u] * v[u]; }
        vs = warp_sum(vs);
        float inv = rsqrtf(vs * (1.0f / Dd) + LN_EPS);
        int p = rr >> 1, e = rr & 1;
        #pragma unroll
        for (int u = 0; u < 8; u++) {
            int k = l + 32 * u;
            ((float*)xs2)[((size_t)p * Dd + k) * 2 + e] = v[u] * inv * gam[k] + bet[k];
        }
    }
    __syncthreads();

    int c = t;
    u64 aK[RLN / 2], aV[RLN / 2];
    #pragma unroll
    for (int p = 0; p < RLN / 2; p++) { aK[p] = 0ULL; aV[p] = 0ULL; }
    const float* wkp = g_WkT + c;
    const float* wvp = g_WvT + c;
    for (int k = 0; k < Dd; k += 2) {
        u64 dk0 = dup2(wkp[(size_t)k * Dd]);
        u64 dk1 = dup2(wkp[(size_t)(k + 1) * Dd]);
        u64 dv0 = dup2(wvp[(size_t)k * Dd]);
        u64 dv1 = dup2(wvp[(size_t)(k + 1) * Dd]);
        #pragma unroll
        for (int p = 0; p < RLN / 2; p++) {
            ulonglong2 x2 = *(const ulonglong2*)&xs2[p][k];
            fma2(aK[p], x2.x, dk0); fma2(aK[p], x2.y, dk1);
            fma2(aV[p], x2.x, dv0); fma2(aV[p], x2.y, dv1);
        }
    }
    float bkc = bk[c], bvc = bv[c];
    #pragma unroll
    for (int p = 0; p < RLN / 2; p++) {
        float2 k2 = unpk(aK[p]);
        float2 v2 = unpk(aV[p]);
        g_K[(size_t)(row0 + 2 * p) * Dd + c]     = k2.x + bkc;
        g_K[(size_t)(row0 + 2 * p + 1) * Dd + c] = k2.y + bkc;
        g_V[(size_t)(row0 + 2 * p) * Dd + c]     = v2.x + bvc;
        g_V[(size_t)(row0 + 2 * p + 1) * Dd + c] = v2.y + bvc;
    }
}

// ---------------- initial Q = LN(slots)@WqT + bq.  grid = 672/RQ --------------
__global__ __launch_bounds__(256)
void q_kernel(const float* __restrict__ gam, const float* __restrict__ bet,
              const float* __restrict__ bq) {
    __shared__ float xs[RQ][Dd];
    int row0 = blockIdx.x * RQ;
    int t = threadIdx.x, w = t >> 5, l = t & 31;
    if (w < RQ) {
        int row = row0 + w;
        const float* src = g_slots + (size_t)row * Dd;
        float v[8]; float s = 0.f;
        #pragma unroll
        for (int u = 0; u < 8; u++) { v[u] = src[l + 32 * u]; s += v[u]; }
        s = warp_sum(s);
        float m = s * (1.0f / Dd);
        float vs = 0.f;
        #pragma unroll
        for (int u = 0; u < 8; u++) { v[u] -= m; vs += v[u] * v[u]; }
        vs = warp_sum(vs);
        float inv = rsqrtf(vs * (1.0f / Dd) + LN_EPS);
        #pragma unroll
        for (int u = 0; u < 8; u++) {
            int k = l + 32 * u;
            xs[w][k] = v[u] * inv * gam[k] + bet[k];
        }
    }
    __syncthreads();
    int c = t;
    float acc[RQ];
    float bqc = bq[c];
    #pragma unroll
    for (int r = 0; r < RQ; r++) acc[r] = bqc;
    const float* wp = g_WqT + c;
    for (int k = 0; k < Dd; k += 4) {
        float w0 = wp[(k + 0) * Dd], w1 = wp[(k + 1) * Dd];
        float w2 = wp[(k + 2) * Dd], w3 = wp[(k + 3) * Dd];
        #pragma unroll
        for (int r = 0; r < RQ; r++) {
            float4 x4 = *(const float4*)&xs[r][k];
            acc[r] = fmaf(x4.x, w0, acc[r]); acc[r] = fmaf(x4.y, w1, acc[r]);
            acc[r] = fmaf(x4.z, w2, acc[r]); acc[r] = fmaf(x4.w, w3, acc[r]);
        }
    }
    #pragma unroll
    for (int r = 0; r < RQ; r++) g_Q[(size_t)(row0 + r) * Dd + c] = acc[r];
}

// ---------------- dots + softmax(+eps).  grid = B * (N/32) --------------------
__global__ __launch_bounds__(256)
void dots_softmax_kernel(int f, int store_out, float* __restrict__ out_attn) {
    __shared__ float Ks[32][68];      // stride 272B: 16B aligned rows
    __shared__ float Qs[Ss][64];
    __shared__ float ds[32][24];
    int b = blockIdx.x / (Nn / 32);
    int j0 = (blockIdx.x % (Nn / 32)) * 32;
    int t = threadIdx.x, w = t >> 5, l = t & 31;
    int jj = l;
    int i0 = w, i1 = w + 8, i2 = w + 16;
    bool has2 = (i2 < Ss);
    u64 A0 = 0ULL, A1 = 0ULL, A2 = 0ULL;

    for (int k0 = 0; k0 < Dd; k0 += 64) {
        for (int idx = t; idx < 32 * 16; idx += 256) {
            int r = idx >> 4, kk4 = (idx & 15) * 4;
            *(float4*)&Ks[r][kk4] =
                *(const float4*)&g_K[((size_t)b * Nn + j0 + r) * Dd + k0 + kk4];
        }
        for (int idx = t; idx < Ss * 16; idx += 256) {
            int r = idx >> 4, kk4 = (idx & 15) * 4;
            *(float4*)&Qs[r][kk4] =
                *(const float4*)&g_Q[((size_t)b * Ss + r) * Dd + k0 + kk4];
        }
        __syncthreads();
        #pragma unroll
        for (int kk = 0; kk < 64; kk += 4) {
            ulonglong2 kp = *(const ulonglong2*)&Ks[jj][kk];
            ulonglong2 q0 = *(const ulonglong2*)&Qs[i0][kk];
            ulonglong2 q1 = *(const ulonglong2*)&Qs[i1][kk];
            fma2(A0, kp.x, q0.x); fma2(A0, kp.y, q0.y);
            fma2(A1, kp.x, q1.x); fma2(A1, kp.y, q1.y);
            if (has2) {
                ulonglong2 q2 = *(const ulonglong2*)&Qs[i2][kk];
                fma2(A2, kp.x, q2.x); fma2(A2, kp.y, q2.y);
            }
        }
        __syncthreads();
    }
    float2 s0 = unpk(A0), s1 = unpk(A1);
    ds[jj][i0] = (s0.x + s0.y) * 0.0625f;
    ds[jj][i1] = (s1.x + s1.y) * 0.0625f;
    if (has2) { float2 s2 = unpk(A2); ds[jj][i2] = (s2.x + s2.y) * 0.0625f; }
    __syncthreads();

    for (int q = w; q < 32; q += 8) {
        float v = (l < Ss) ? ds[q][l] : -3.4e38f;
        float mx = warp_max(v);
        float e = (l < Ss) ? expf(v - mx) : 0.f;
        float sm = warp_sum(e);
        if (l < Ss) {
            float a = e / sm + EPSs;
            g_At[((size_t)b * Nn + j0 + q) * Ss + l] = a;
            if (store_out)
                out_attn[(((size_t)b * NFr + f) * Ss + l) * Nn + j0 + q] = a;
        }
    }
}

// ------- fused: updates + GRU + LN + FF + mlp2 + next-iter Q ------------------
// grid = B * 3 = 96 blocks, 256 threads.  Rows packed in pairs (pair3 hi = dup row6).
__global__ __launch_bounds__(256)
void slot_update_kernel(const float* __restrict__ b_ih, const float* __restrict__ b_hh,
                        const float* __restrict__ g_ff, const float* __restrict__ be_ff,
                        const float* __restrict__ b1, const float* __restrict__ b2,
                        const float* __restrict__ g_sl, const float* __restrict__ be_sl,
                        const float* __restrict__ bq) {
    __shared__ float2 asp[4][Nn];     // (A[2p][j], A[2p+1][j])
    __shared__ float2 usp[4][Dd];
    __shared__ float2 hsp[4][Dd];
    __shared__ float2 fsp[4][Dd];
    __shared__ float inv_[8];

    int b = blockIdx.x / 3;
    int i0 = (blockIdx.x % 3) * RS;
    int t = threadIdx.x, w = t >> 5, l = t & 31;
    int c = t;

    // Phase A: stage attn into pair layout; logical rows 0..7 (7 = dup of 6)
    for (int idx = t; idx < 8 * Nn; idx += 256) {
        int lr = idx & 7, j = idx >> 3;
        int row = (lr < 7) ? lr : 6;
        ((float*)asp)[((size_t)(lr >> 1) * Nn + j) * 2 + (lr & 1)] =
            g_At[((size_t)b * Nn + j) * Ss + i0 + row];
    }
    __syncthreads();
    // per-logical-row sums (warp w handles logical row w)
    {
        int p = w >> 1, e = w & 1;
        float s = 0.f;
        #pragma unroll
        for (int u = 0; u < Nn / 32; u++)
            s += ((const float*)asp)[((size_t)p * Nn + l + 32 * u) * 2 + e];
        s = warp_sum(s);
        if (l == 0) inv_[w] = 1.0f / s;
    }
    // h0 pairs (clamp hi row)
    float h0lo[4], h0hi[4];
    #pragma unroll
    for (int p = 0; p < 4; p++) {
        int rlo = 2 * p, rhi = (2 * p + 1 < RS) ? 2 * p + 1 : RS - 1;
        h0lo[p] = g_slots[((size_t)b * Ss + i0 + rlo) * Dd + c];
        h0hi[p] = g_slots[((size_t)b * Ss + i0 + rhi) * Dd + c];
    }
    __syncthreads();   // asp + inv_ ready

    // Phase B: updates = (A/rowsum) @ V
    u64 accU[4];
    #pragma unroll
    for (int p = 0; p < 4; p++) accU[p] = 0ULL;
    const float* vp = g_V + (size_t)b * Nn * Dd + c;
    for (int j = 0; j < Nn; j += 2) {
        u64 vd0 = dup2(vp[(size_t)j * Dd]);
        u64 vd1 = dup2(vp[(size_t)(j + 1) * Dd]);
        #pragma unroll
        for (int p = 0; p < 4; p++) {
            ulonglong2 a2 = *(const ulonglong2*)&asp[p][j];
            fma2(accU[p], a2.x, vd0);
            fma2(accU[p], a2.y, vd1);
        }
    }
    #pragma unroll
    for (int p = 0; p < 4; p++) {
        float2 u2 = unpk(accU[p]);
        usp[p][c] = make_float2(u2.x * inv_[2 * p], u2.y * inv_[2 * p + 1]);
        hsp[p][c] = make_float2(h0lo[p], h0hi[p]);
    }
    __syncthreads();

    // Phase C: GRU gates (6 packed accumulators x 4 pairs)
    u64 a_ir[4], a_iz[4], a_in[4], a_hr[4], a_hz[4], a_hn[4];
    #pragma unroll
    for (int p = 0; p < 4; p++) {
        a_ir[p] = 0ULL; a_iz[p] = 0ULL; a_in[p] = 0ULL;
        a_hr[p] = 0ULL; a_hz[p] = 0ULL; a_hn[p] = 0ULL;
    }
    const float* wip = g_WihT + c;
    const float* whp = g_WhhT + c;
    for (int k = 0; k < Dd; k += 2) {
        const float* w0 = wip + (size_t)k * (3 * Dd);
        const float* w1 = w0 + 3 * Dd;
        u64 dir0 = dup2(w0[0]),       dir1 = dup2(w1[0]);
        u64 diz0 = dup2(w0[Dd]),      diz1 = dup2(w1[Dd]);
        u64 din0 = dup2(w0[2 * Dd]),  din1 = dup2(w1[2 * Dd]);
        const float* v0 = whp + (size_t)k * (3 * Dd);
        const float* v1 = v0 + 3 * Dd;
        u64 dhr0 = dup2(v0[0]),       dhr1 = dup2(v1[0]);
        u64 dhz0 = dup2(v0[Dd]),      dhz1 = dup2(v1[Dd]);
        u64 dhn0 = dup2(v0[2 * Dd]),  dhn1 = dup2(v1[2 * Dd]);
        #pragma unroll
        for (int p = 0; p < 4; p++) {
            ulonglong2 u2 = *(const ulonglong2*)&usp[p][k];
            ulonglong2 h2 = *(const ulonglong2*)&hsp[p][k];
            fma2(a_ir[p], u2.x, dir0); fma2(a_ir[p], u2.y, dir1);
            fma2(a_iz[p], u2.x, diz0); fma2(a_iz[p], u2.y, diz1);
            fma2(a_in[p], u2.x, din0); fma2(a_in[p], u2.y, din1);
            fma2(a_hr[p], h2.x, dhr0); fma2(a_hr[p], h2.y, dhr1);
            fma2(a_hz[p], h2.x, dhz0); fma2(a_hz[p], h2.y, dhz1);
            fma2(a_hn[p], h2.x, dhn0); fma2(a_hn[p], h2.y, dhn1);
        }
    }
    float bir = b_ih[c], biz = b_ih[Dd + c], bin = b_ih[2 * Dd + c];
    float bhr = b_hh[c], bhz = b_hh[Dd + c], bhn = b_hh[2 * Dd + c];
    float hnlo[4], hnhi[4];
    #pragma unroll
    for (int p = 0; p < 4; p++) {
        float2 ir2 = unpk(a_ir[p]), iz2 = unpk(a_iz[p]), in2 = unpk(a_in[p]);
        float2 hr2 = unpk(a_hr[p]), hz2 = unpk(a_hz[p]), hn2 = unpk(a_hn[p]);
        {
            float rg = 1.f / (1.f + expf(-(ir2.x + bir + hr2.x + bhr)));
            float zg = 1.f / (1.f + expf(-(iz2.x + biz + hz2.x + bhz)));
            float ng = tanhf(in2.x + bin + rg * (hn2.x + bhn));
            hnlo[p] = (1.f - zg) * ng + zg * h0lo[p];
        }
        {
            float rg = 1.f / (1.f + expf(-(ir2.y + bir + hr2.y + bhr)));
            float zg = 1.f / (1.f + expf(-(iz2.y + biz + hz2.y + bhz)));
            float ng = tanhf(in2.y + bin + rg * (hn2.y + bhn));
            hnhi[p] = (1.f - zg) * ng + zg * h0hi[p];
        }
    }
    __syncthreads();           // all usp/hsp reads done
    #pragma unroll
    for (int p = 0; p < 4; p++) usp[p][c] = make_float2(hnlo[p], hnhi[p]);
    __syncthreads();

    // Phase D: LN(hnew; g_ff) -> hsp (warp w handles logical row w)
    {
        int p = w >> 1, e = w & 1;
        float v[8]; float s = 0.f;
        #pragma unroll
        for (int u = 0; u < 8; u++) {
            v[u] = ((const float*)usp)[((size_t)p * Dd + l + 32 * u) * 2 + e];
            s += v[u];
        }
        s = warp_sum(s);
        float m = s * (1.0f / Dd);
        float vs = 0.f;
        #pragma unroll
        for (int u = 0; u < 8; u++) { v[u] -= m; vs += v[u] * v[u]; }
        vs = warp_sum(vs);
        float iv = rsqrtf(vs * (1.0f / Dd) + LN_EPS);
        #pragma unroll
        for (int u = 0; u < 8; u++) {
            int k = l + 32 * u;
            ((float*)hsp)[((size_t)p * Dd + k) * 2 + e] = v[u] * iv * g_ff[k] + be_ff[k];
        }
    }
    __syncthreads();

    // Phase E: FF = relu(LN @ W1T + b1) -> fsp
    {
        u64 aF[4];
        #pragma unroll
        for (int p = 0; p < 4; p++) aF[p] = 0ULL;
        const float* wp = g_W1T + c;
        for (int k = 0; k < Dd; k += 2) {
            u64 d0 = dup2(wp[(size_t)k * Dd]);
            u64 d1 = dup2(wp[(size_t)(k + 1) * Dd]);
            #pragma unroll
            for (int p = 0; p < 4; p++) {
                ulonglong2 x2 = *(const ulonglong2*)&hsp[p][k];
                fma2(aF[p], x2.x, d0); fma2(aF[p], x2.y, d1);
            }
        }
        float b1c = b1[c];
        #pragma unroll
        for (int p = 0; p < 4; p++) {
            float2 f2 = unpk(aF[p]);
            fsp[p][c] = make_float2(fmaxf(f2.x + b1c, 0.f), fmaxf(f2.y + b1c, 0.f));
        }
    }
    __syncthreads();

    // Phase F: slots_new = hnew + fsp @ W2T + b2 -> global, staged in usp
    {
        u64 aO[4];
        #pragma unroll
        for (int p = 0; p < 4; p++) aO[p] = 0ULL;
        const float* wp = g_W2T + c;
        for (int k = 0; k < Dd; k += 2) {
            u64 d0 = dup2(wp[(size_t)k * Dd]);
            u64 d1 = dup2(wp[(size_t)(k + 1) * Dd]);
            #pragma unroll
            for (int p = 0; p < 4; p++) {
                ulonglong2 x2 = *(const ulonglong2*)&fsp[p][k];
                fma2(aO[p], x2.x, d0); fma2(aO[p], x2.y, d1);
            }
        }
        float b2c = b2[c];
        __syncthreads();       // fsp reads done before Phase G rewrites fsp
        #pragma unroll
        for (int p = 0; p < 4; p++) {
            float2 o2 = unpk(aO[p]);
            float snlo = hnlo[p] + o2.x + b2c;
            float snhi = hnhi[p] + o2.y + b2c;
            int rlo = i0 + 2 * p;
            g_slots[((size_t)b * Ss + rlo) * Dd + c] = snlo;
            if (2 * p + 1 < RS) g_slots[((size_t)b * Ss + rlo + 1) * Dd + c] = snhi;
            usp[p][c] = make_float2(snlo, snhi);
        }
    }
    __syncthreads();

    // Phase G: next-iter Q = LN(slots_new; g_sl) @ WqT + bq
    {
        int p = w >> 1, e = w & 1;
        float v[8]; float s = 0.f;
        #pragma unroll
        for (int u = 0; u < 8; u++) {
            v[u] = ((const float*)usp)[((size_t)p * Dd + l + 32 * u) * 2 + e];
            s += v[u];
        }
        s = warp_sum(s);
        float m = s * (1.0f / Dd);
        float vs = 0.f;
        #pragma unroll
        for (int u = 0; u < 8; u++) { v[u] -= m; vs += v[u] * v[u]; }
        vs = warp_sum(vs);
        float iv = rsqrtf(vs * (1.0f / Dd) + LN_EPS);
        #pragma unroll
        for (int u = 0; u < 8; u++) {
            int k = l + 32 * u;
            ((float*)fsp)[((size_t)p * Dd + k) * 2 + e] = v[u] * iv * g_sl[k] + be_sl[k];
        }
    }
    __syncthreads();
    {
        u64 aQ[4];
        #pragma unroll
        for (int p = 0; p < 4; p++) aQ[p] = 0ULL;
        const float* wp = g_WqT + c;
        for (int k = 0; k < Dd; k += 2) {
            u64 d0 = dup2(wp[(size_t)k * Dd]);
            u64 d1 = dup2(wp[(size_t)(k + 1) * Dd]);
            #pragma unroll
            for (int p = 0; p < 4; p++) {
                ulonglong2 x2 = *(const ulonglong2*)&fsp[p][k];
                fma2(aQ[p], x2.x, d0); fma2(aQ[p], x2.y, d1);
            }
        }
        float bqc = bq[c];
        #pragma unroll
        for (int p = 0; p < 4; p++) {
            float2 q2 = unpk(aQ[p]);
            int rlo = i0 + 2 * p;
            g_Q[((size_t)b * Ss + rlo) * Dd + c] = q2.x + bqc;
            if (2 * p + 1 < RS) g_Q[((size_t)b * Ss + rlo + 1) * Dd + c] = q2.y + bqc;
        }
    }
}

// ---------------- output slots ------------------------------------------------
__global__ void out_slots_kernel(float* __restrict__ out) {
    int idx = blockIdx.x * blockDim.x + threadIdx.x;
    int d = idx & (Dd - 1);
    int rest = idx / Dd;
    int s = rest % NA;
    int b = rest / NA;
    out[idx] = g_slots[((size_t)b * Ss + s) * Dd + d];
}

// ---------------- launch ------------------------------------------------------
extern "C" void kernel_launch(void* const* d_in, const int* in_sizes, int n_in,
                              void* d_out, int out_size) {
    const float* inputs = (const float*)d_in[0];
    const float* noise  = (const float*)d_in[1];
    const float* mu     = (const float*)d_in[2];
    const float* sigma  = (const float*)d_in[3];
    const float* Wq     = (const float*)d_in[4];
    const float* bq     = (const float*)d_in[5];
    const float* Wk     = (const float*)d_in[6];
    const float* bk     = (const float*)d_in[7];
    const float* Wv     = (const float*)d_in[8];
    const float* bv     = (const float*)d_in[9];
    const float* W1     = (const float*)d_in[10];
    const float* b1     = (const float*)d_in[11];
    const float* W2     = (const float*)d_in[12];
    const float* b2     = (const float*)d_in[13];
    const float* W_ih   = (const float*)d_in[14];
    const float* b_ih   = (const float*)d_in[15];
    const float* W_hh   = (const float*)d_in[16];
    const float* b_hh   = (const float*)d_in[17];
    const float* gin    = (const float*)d_in[18];
    const float* bein   = (const float*)d_in[19];
    const float* gsl    = (const float*)d_in[20];
    const float* besl   = (const float*)d_in[21];
    const float* gff    = (const float*)d_in[22];
    const float* beff   = (const float*)d_in[23];

    float* out = (float*)d_out;
    float* out_attn = out + (size_t)Bz * NA * Dd;

    transpose_all_kernel<<<704, dim3(32, 8)>>>(Wq, Wk, Wv, W1, W2, W_ih, W_hh);
    init_slots_kernel<<<(Bz * Ss * Dd) / 256, 256>>>(noise, mu, sigma);
    q_kernel<<<(Bz * Ss) / RQ, 256>>>(gsl, besl, bq);

    for (int f = 0; f < NFr; f++) {
        ln_kv_kernel<<<(Bz * Nn) / RLN, 256>>>(inputs, f, gin, bein, bk, bv);
        for (int it = 0; it < 3; it++) {
            dots_softmax_kernel<<<Bz * (Nn / 32), 256>>>(f, (it == 2) ? 1 : 0, out_attn);
            slot_update_kernel<<<Bz * 3, 256>>>(b_ih, b_hh, gff, beff,
                                                b1, b2, gsl, besl, bq);
        }
    }

    out_slots_kernel<<<(Bz * NA * Dd) / 256, 256>>>(out);
}

// round 4
// speedup vs baseline: 23.0524x; 1.0399x over previous
#include <cuda_runtime.h>
#include <math.h>

#define Bz 32
#define NFr 16
#define Dd 256
#define Ss 21
#define Nn 192
#define NA 20
#define EPSs 1e-8f
#define LN_EPS 1e-5f
#define RLN 24   // rows per block in kv_all (12 pairs)
#define RQ 8
#define RS 7     // slot rows per block (4 pairs, last hi = dup)

typedef unsigned long long u64;

// ---------------- packed f32x2 helpers ---------------------------------------
__device__ __forceinline__ void fma2(u64& d, u64 a, u64 b) {
    asm("fma.rn.f32x2 %0, %1, %2, %0;" : "+l"(d) : "l"(a), "l"(b));
}
__device__ __forceinline__ u64 dup2(float v) {
    u64 r; asm("mov.b64 %0, {%1, %1};" : "=l"(r) : "f"(v)); return r;
}
__device__ __forceinline__ float2 unpk(u64 v) {
    float lo, hi; asm("mov.b64 {%0, %1}, %2;" : "=f"(lo), "=f"(hi) : "l"(v));
    return make_float2(lo, hi);
}

// ---------------- scratch ----------------------------------------------------
__device__ float g_K[(size_t)Bz * NFr * Nn * Dd];   // [b][f][n][d]  ~100MB
__device__ float g_V[(size_t)Bz * NFr * Nn * Dd];
__device__ float g_slots[Bz * Ss * Dd];
__device__ float g_Q[Bz * Ss * Dd];
__device__ float g_At[Bz * Nn * Ss];                // attn_ori^T: [b][j][i]
// pair-interleaved transposed weights: WT2[kp][c] = (W[c][2kp], W[c][2kp+1])
__device__ float2 g_WqT2[128 * Dd];
__device__ float2 g_WkT2[128 * Dd];
__device__ float2 g_WvT2[128 * Dd];
__device__ float2 g_W1T2[128 * Dd];
__device__ float2 g_W2T2[128 * Dd];
__device__ float2 g_WihT2[128 * 3 * Dd];            // [kp][g], g<768
__device__ float2 g_WhhT2[128 * 3 * Dd];

// ---------------- fused f2-transpose of all 7 weight matrices ----------------
// square mats: src f2-view [256][128] -> dst [128][256]; GRU: [768][128]->[128][768]
__global__ void transpose2_all_kernel(const float* __restrict__ Wq, const float* __restrict__ Wk,
                                      const float* __restrict__ Wv, const float* __restrict__ W1,
                                      const float* __restrict__ W2, const float* __restrict__ Wih,
                                      const float* __restrict__ Whh) {
    __shared__ float2 tile[32][33];
    int bid = blockIdx.x;
    const float2* src; float2* dst; int R; int tloc;
    if (bid < 160) {
        int m = bid >> 5; tloc = bid & 31; R = 256;
        switch (m) {
            case 0: src = (const float2*)Wq; dst = g_WqT2; break;
            case 1: src = (const float2*)Wk; dst = g_WkT2; break;
            case 2: src = (const float2*)Wv; dst = g_WvT2; break;
            case 3: src = (const float2*)W1; dst = g_W1T2; break;
            default: src = (const float2*)W2; dst = g_W2T2; break;
        }
    } else {
        int m = (bid - 160) / 96; tloc = (bid - 160) % 96; R = 768;
        src = (const float2*)(m == 0 ? Wih : Whh);
        dst = (m == 0 ? g_WihT2 : g_WhhT2);
    }
    int bx = (tloc & 3) * 32;        // f2-col tile (kp)
    int by = (tloc >> 2) * 32;       // row tile (c / gate col)
    int tx = threadIdx.x, ty = threadIdx.y;
    #pragma unroll
    for (int i = 0; i < 32; i += 8)
        tile[ty + i][tx] = src[(size_t)(by + ty + i) * 128 + bx + tx];
    __syncthreads();
    #pragma unroll
    for (int i = 0; i < 32; i += 8)
        dst[(size_t)(bx + ty + i) * R + by + tx] = tile[tx][ty + i];
}

// ---------------- init slots --------------------------------------------------
__global__ void init_slots_kernel(const float* __restrict__ noise,
                                  const float* __restrict__ mu,
                                  const float* __restrict__ sigma) {
    int idx = blockIdx.x * blockDim.x + threadIdx.x;
    int d = idx & (Dd - 1);
    g_slots[idx] = mu[d] + sigma[d] * noise[idx];
}

// ---------------- warp helpers ------------------------------------------------
__device__ __forceinline__ float warp_sum(float v) {
    #pragma unroll
    for (int o = 16; o > 0; o >>= 1) v += __shfl_xor_sync(0xffffffffu, v, o);
    return v;
}
__device__ __forceinline__ float warp_max(float v) {
    #pragma unroll
    for (int o = 16; o > 0; o >>= 1) v = fmaxf(v, __shfl_xor_sync(0xffffffffu, v, o));
    return v;
}

// ------- LN(all frames) -> K,V.  grid = B*NF*N/RLN = 4096, 256 thr ------------
__global__ __launch_bounds__(256)
void kv_all_kernel(const float* __restrict__ inputs,
                   const float* __restrict__ gam, const float* __restrict__ bet,
                   const float* __restrict__ bk, const float* __restrict__ bv) {
    __shared__ float2 xs2[RLN / 2][Dd];   // pair p = rows (2p, 2p+1)
    int row0 = blockIdx.x * RLN;          // flat over [b][f][n]
    int t = threadIdx.x, w = t >> 5, l = t & 31;

    for (int rr = w; rr < RLN; rr += 8) {
        int row = row0 + rr;
        const float* src = inputs + (size_t)row * Dd;
        float v[8]; float s = 0.f;
        #pragma unroll
        for (int u = 0; u < 8; u++) { v[u] = src[l + 32 * u]; s += v[u]; }
        s = warp_sum(s);
        float m = s * (1.0f / Dd);
        float vs = 0.f;
        #pragma unroll
        for (int u = 0; u < 8; u++) { v[u] -= m; vs += v[u] * v[u]; }
        vs = warp_sum(vs);
        float inv = rsqrtf(vs * (1.0f / Dd) + LN_EPS);
        int p = rr >> 1, e = rr & 1;
        #pragma unroll
        for (int u = 0; u < 8; u++) {
            int k = l + 32 * u;
            ((float*)xs2)[((size_t)p * Dd + k) * 2 + e] = v[u] * inv * gam[k] + bet[k];
        }
    }
    __syncthreads();

    int c = t;
    u64 aK[RLN / 2], aV[RLN / 2];
    #pragma unroll
    for (int p = 0; p < RLN / 2; p++) { aK[p] = 0ULL; aV[p] = 0ULL; }
    const float2* wk2 = g_WkT2 + c;
    const float2* wv2 = g_WvT2 + c;
    for (int kp = 0; kp < 128; kp++) {
        float2 wk = wk2[(size_t)kp * Dd];
        float2 wv = wv2[(size_t)kp * Dd];
        u64 dk0 = dup2(wk.x), dk1 = dup2(wk.y);
        u64 dv0 = dup2(wv.x), dv1 = dup2(wv.y);
        int k = 2 * kp;
        #pragma unroll
        for (int p = 0; p < RLN / 2; p++) {
            ulonglong2 x2 = *(const ulonglong2*)&xs2[p][k];
            fma2(aK[p], x2.x, dk0); fma2(aK[p], x2.y, dk1);
            fma2(aV[p], x2.x, dv0); fma2(aV[p], x2.y, dv1);
        }
    }
    float bkc = bk[c], bvc = bv[c];
    #pragma unroll
    for (int p = 0; p < RLN / 2; p++) {
        float2 k2 = unpk(aK[p]);
        float2 v2 = unpk(aV[p]);
        g_K[(size_t)(row0 + 2 * p) * Dd + c]     = k2.x + bkc;
        g_K[(size_t)(row0 + 2 * p + 1) * Dd + c] = k2.y + bkc;
        g_V[(size_t)(row0 + 2 * p) * Dd + c]     = v2.x + bvc;
        g_V[(size_t)(row0 + 2 * p + 1) * Dd + c] = v2.y + bvc;
    }
}

// ---------------- initial Q = LN(slots)@WqT + bq.  grid = 672/RQ --------------
__global__ __launch_bounds__(256)
void q_kernel(const float* __restrict__ gam, const float* __restrict__ bet,
              const float* __restrict__ bq) {
    __shared__ float xs[RQ][Dd];
    int row0 = blockIdx.x * RQ;
    int t = threadIdx.x, w = t >> 5, l = t & 31;
    if (w < RQ) {
        int row = row0 + w;
        const float* src = g_slots + (size_t)row * Dd;
        float v[8]; float s = 0.f;
        #pragma unroll
        for (int u = 0; u < 8; u++) { v[u] = src[l + 32 * u]; s += v[u]; }
        s = warp_sum(s);
        float m = s * (1.0f / Dd);
        float vs = 0.f;
        #pragma unroll
        for (int u = 0; u < 8; u++) { v[u] -= m; vs += v[u] * v[u]; }
        vs = warp_sum(vs);
        float inv = rsqrtf(vs * (1.0f / Dd) + LN_EPS);
        #pragma unroll
        for (int u = 0; u < 8; u++) {
            int k = l + 32 * u;
            xs[w][k] = v[u] * inv * gam[k] + bet[k];
        }
    }
    __syncthreads();
    int c = t;
    float acc[RQ];
    float bqc = bq[c];
    #pragma unroll
    for (int r = 0; r < RQ; r++) acc[r] = bqc;
    const float2* wp = g_WqT2 + c;
    for (int kp = 0; kp < 128; kp++) {
        float2 w2 = wp[(size_t)kp * Dd];
        int k = 2 * kp;
        #pragma unroll
        for (int r = 0; r < RQ; r++) {
            float2 x2 = *(const float2*)&xs[r][k];
            acc[r] = fmaf(x2.x, w2.x, acc[r]);
            acc[r] = fmaf(x2.y, w2.y, acc[r]);
        }
    }
    #pragma unroll
    for (int r = 0; r < RQ; r++) g_Q[(size_t)(row0 + r) * Dd + c] = acc[r];
}

// ---------------- dots + softmax(+eps).  grid = B * (N/32) --------------------
__global__ __launch_bounds__(256)
void dots_softmax_kernel(int f, int store_out, float* __restrict__ out_attn) {
    __shared__ float Ks[32][68];
    __shared__ float Qs[Ss][64];
    __shared__ float ds[32][24];
    int b = blockIdx.x / (Nn / 32);
    int j0 = (blockIdx.x % (Nn / 32)) * 32;
    int t = threadIdx.x, w = t >> 5, l = t & 31;
    int jj = l;
    int i0 = w, i1 = w + 8, i2 = w + 16;
    bool has2 = (i2 < Ss);
    u64 A0 = 0ULL, A1 = 0ULL, A2 = 0ULL;
    const float* Kbase = g_K + (((size_t)b * NFr + f) * Nn) * Dd;

    for (int k0 = 0; k0 < Dd; k0 += 64) {
        for (int idx = t; idx < 32 * 16; idx += 256) {
            int r = idx >> 4, kk4 = (idx & 15) * 4;
            *(float4*)&Ks[r][kk4] =
                *(const float4*)&Kbase[(size_t)(j0 + r) * Dd + k0 + kk4];
        }
        for (int idx = t; idx < Ss * 16; idx += 256) {
            int r = idx >> 4, kk4 = (idx & 15) * 4;
            *(float4*)&Qs[r][kk4] =
                *(const float4*)&g_Q[((size_t)b * Ss + r) * Dd + k0 + kk4];
        }
        __syncthreads();
        #pragma unroll
        for (int kk = 0; kk < 64; kk += 4) {
            ulonglong2 kp = *(const ulonglong2*)&Ks[jj][kk];
            ulonglong2 q0 = *(const ulonglong2*)&Qs[i0][kk];
            ulonglong2 q1 = *(const ulonglong2*)&Qs[i1][kk];
            fma2(A0, kp.x, q0.x); fma2(A0, kp.y, q0.y);
            fma2(A1, kp.x, q1.x); fma2(A1, kp.y, q1.y);
            if (has2) {
                ulonglong2 q2 = *(const ulonglong2*)&Qs[i2][kk];
                fma2(A2, kp.x, q2.x); fma2(A2, kp.y, q2.y);
            }
        }
        __syncthreads();
    }
    float2 s0 = unpk(A0), s1 = unpk(A1);
    ds[jj][i0] = (s0.x + s0.y) * 0.0625f;
    ds[jj][i1] = (s1.x + s1.y) * 0.0625f;
    if (has2) { float2 s2 = unpk(A2); ds[jj][i2] = (s2.x + s2.y) * 0.0625f; }
    __syncthreads();

    for (int q = w; q < 32; q += 8) {
        float v = (l < Ss) ? ds[q][l] : -3.4e38f;
        float mx = warp_max(v);
        float e = (l < Ss) ? expf(v - mx) : 0.f;
        float sm = warp_sum(e);
        if (l < Ss) {
            float a = e / sm + EPSs;
            g_At[((size_t)b * Nn + j0 + q) * Ss + l] = a;
            if (store_out)
                out_attn[(((size_t)b * NFr + f) * Ss + l) * Nn + j0 + q] = a;
        }
    }
}

// ------- fused: updates + GRU + LN + FF + mlp2 + next-iter Q ------------------
// grid = B * 3 = 96 blocks, 256 threads. Rows in pairs (pair3 hi = dup row6).
__global__ __launch_bounds__(256)
void slot_update_kernel(int f,
                        const float* __restrict__ b_ih, const float* __restrict__ b_hh,
                        const float* __restrict__ g_ff, const float* __restrict__ be_ff,
                        const float* __restrict__ b1, const float* __restrict__ b2,
                        const float* __restrict__ g_sl, const float* __restrict__ be_sl,
                        const float* __restrict__ bq) {
    __shared__ float2 asp[4][Nn];
    __shared__ float2 usp[4][Dd];
    __shared__ float2 hsp[4][Dd];
    __shared__ float2 fsp[4][Dd];
    __shared__ float inv_[8];

    int b = blockIdx.x / 3;
    int i0 = (blockIdx.x % 3) * RS;
    int t = threadIdx.x, w = t >> 5, l = t & 31;
    int c = t;

    // Phase A: stage attn into pair layout; logical rows 0..7 (7 = dup of 6)
    for (int idx = t; idx < 8 * Nn; idx += 256) {
        int lr = idx & 7, j = idx >> 3;
        int row = (lr < 7) ? lr : 6;
        ((float*)asp)[((size_t)(lr >> 1) * Nn + j) * 2 + (lr & 1)] =
            g_At[((size_t)b * Nn + j) * Ss + i0 + row];
    }
    __syncthreads();
    {
        int p = w >> 1, e = w & 1;
        float s = 0.f;
        #pragma unroll
        for (int u = 0; u < Nn / 32; u++)
            s += ((const float*)asp)[((size_t)p * Nn + l + 32 * u) * 2 + e];
        s = warp_sum(s);
        if (l == 0) inv_[w] = 1.0f / s;
    }
    float h0lo[4], h0hi[4];
    #pragma unroll
    for (int p = 0; p < 4; p++) {
        int rlo = 2 * p, rhi = (2 * p + 1 < RS) ? 2 * p + 1 : RS - 1;
        h0lo[p] = g_slots[((size_t)b * Ss + i0 + rlo) * Dd + c];
        h0hi[p] = g_slots[((size_t)b * Ss + i0 + rhi) * Dd + c];
    }
    __syncthreads();

    // Phase B: updates = (A/rowsum) @ V
    u64 accU[4];
    #pragma unroll
    for (int p = 0; p < 4; p++) accU[p] = 0ULL;
    const float* vp = g_V + (((size_t)b * NFr + f) * Nn) * Dd + c;
    for (int j = 0; j < Nn; j += 2) {
        u64 vd0 = dup2(vp[(size_t)j * Dd]);
        u64 vd1 = dup2(vp[(size_t)(j + 1) * Dd]);
        #pragma unroll
        for (int p = 0; p < 4; p++) {
            ulonglong2 a2 = *(const ulonglong2*)&asp[p][j];
            fma2(accU[p], a2.x, vd0);
            fma2(accU[p], a2.y, vd1);
        }
    }
    #pragma unroll
    for (int p = 0; p < 4; p++) {
        float2 u2 = unpk(accU[p]);
        usp[p][c] = make_float2(u2.x * inv_[2 * p], u2.y * inv_[2 * p + 1]);
        hsp[p][c] = make_float2(h0lo[p], h0hi[p]);
    }
    __syncthreads();

    // Phase C: GRU gates
    u64 a_ir[4], a_iz[4], a_in[4], a_hr[4], a_hz[4], a_hn[4];
    #pragma unroll
    for (int p = 0; p < 4; p++) {
        a_ir[p] = 0ULL; a_iz[p] = 0ULL; a_in[p] = 0ULL;
        a_hr[p] = 0ULL; a_hz[p] = 0ULL; a_hn[p] = 0ULL;
    }
    const float2* wip2 = g_WihT2 + c;
    const float2* whp2 = g_WhhT2 + c;
    for (int kp = 0; kp < 128; kp++) {
        float2 wr_ = wip2[(size_t)kp * (3 * Dd)];
        float2 wz_ = wip2[(size_t)kp * (3 * Dd) + Dd];
        float2 wn_ = wip2[(size_t)kp * (3 * Dd) + 2 * Dd];
        float2 vr_ = whp2[(size_t)kp * (3 * Dd)];
        float2 vz_ = whp2[(size_t)kp * (3 * Dd) + Dd];
        float2 vn_ = whp2[(size_t)kp * (3 * Dd) + 2 * Dd];
        u64 dir0 = dup2(wr_.x), dir1 = dup2(wr_.y);
        u64 diz0 = dup2(wz_.x), diz1 = dup2(wz_.y);
        u64 din0 = dup2(wn_.x), din1 = dup2(wn_.y);
        u64 dhr0 = dup2(vr_.x), dhr1 = dup2(vr_.y);
        u64 dhz0 = dup2(vz_.x), dhz1 = dup2(vz_.y);
        u64 dhn0 = dup2(vn_.x), dhn1 = dup2(vn_.y);
        int k = 2 * kp;
        #pragma unroll
        for (int p = 0; p < 4; p++) {
            ulonglong2 u2 = *(const ulonglong2*)&usp[p][k];
            ulonglong2 h2 = *(const ulonglong2*)&hsp[p][k];
            fma2(a_ir[p], u2.x, dir0); fma2(a_ir[p], u2.y, dir1);
            fma2(a_iz[p], u2.x, diz0); fma2(a_iz[p], u2.y, diz1);
            fma2(a_in[p], u2.x, din0); fma2(a_in[p], u2.y, din1);
            fma2(a_hr[p], h2.x, dhr0); fma2(a_hr[p], h2.y, dhr1);
            fma2(a_hz[p], h2.x, dhz0); fma2(a_hz[p], h2.y, dhz1);
            fma2(a_hn[p], h2.x, dhn0); fma2(a_hn[p], h2.y, dhn1);
        }
    }
    float bir = b_ih[c], biz = b_ih[Dd + c], bin = b_ih[2 * Dd + c];
    float bhr = b_hh[c], bhz = b_hh[Dd + c], bhn = b_hh[2 * Dd + c];
    float hnlo[4], hnhi[4];
    #pragma unroll
    for (int p = 0; p < 4; p++) {
        float2 ir2 = unpk(a_ir[p]), iz2 = unpk(a_iz[p]), in2 = unpk(a_in[p]);
        float2 hr2 = unpk(a_hr[p]), hz2 = unpk(a_hz[p]), hn2 = unpk(a_hn[p]);
        {
            float rg = 1.f / (1.f + expf(-(ir2.x + bir + hr2.x + bhr)));
            float zg = 1.f / (1.f + expf(-(iz2.x + biz + hz2.x + bhz)));
            float ng = tanhf(in2.x + bin + rg * (hn2.x + bhn));
            hnlo[p] = (1.f - zg) * ng + zg * h0lo[p];
        }
        {
            float rg = 1.f / (1.f + expf(-(ir2.y + bir + hr2.y + bhr)));
            float zg = 1.f / (1.f + expf(-(iz2.y + biz + hz2.y + bhz)));
            float ng = tanhf(in2.y + bin + rg * (hn2.y + bhn));
            hnhi[p] = (1.f - zg) * ng + zg * h0hi[p];
        }
    }
    __syncthreads();
    #pragma unroll
    for (int p = 0; p < 4; p++) usp[p][c] = make_float2(hnlo[p], hnhi[p]);
    __syncthreads();

    // Phase D: LN(hnew; g_ff) -> hsp
    {
        int p = w >> 1, e = w & 1;
        float v[8]; float s = 0.f;
        #pragma unroll
        for (int u = 0; u < 8; u++) {
            v[u] = ((const float*)usp)[((size_t)p * Dd + l + 32 * u) * 2 + e];
            s += v[u];
        }
        s = warp_sum(s);
        float m = s * (1.0f / Dd);
        float vs = 0.f;
        #pragma unroll
        for (int u = 0; u < 8; u++) { v[u] -= m; vs += v[u] * v[u]; }
        vs = warp_sum(vs);
        float iv = rsqrtf(vs * (1.0f / Dd) + LN_EPS);
        #pragma unroll
        for (int u = 0; u < 8; u++) {
            int k = l + 32 * u;
            ((float*)hsp)[((size_t)p * Dd + k) * 2 + e] = v[u] * iv * g_ff[k] + be_ff[k];
        }
    }
    __syncthreads();

    // Phase E: FF = relu(LN @ W1T + b1) -> fsp
    {
        u64 aF[4];
        #pragma unroll
        for (int p = 0; p < 4; p++) aF[p] = 0ULL;
        const float2* wp = g_W1T2 + c;
        for (int kp = 0; kp < 128; kp++) {
            float2 w2 = wp[(size_t)kp * Dd];
            u64 d0 = dup2(w2.x), d1 = dup2(w2.y);
            int k = 2 * kp;
            #pragma unroll
            for (int p = 0; p < 4; p++) {
                ulonglong2 x2 = *(const ulonglong2*)&hsp[p][k];
                fma2(aF[p], x2.x, d0); fma2(aF[p], x2.y, d1);
            }
        }
        float b1c = b1[c];
        #pragma unroll
        for (int p = 0; p < 4; p++) {
            float2 f2 = unpk(aF[p]);
            fsp[p][c] = make_float2(fmaxf(f2.x + b1c, 0.f), fmaxf(f2.y + b1c, 0.f));
        }
    }
    __syncthreads();

    // Phase F: slots_new = hnew + fsp @ W2T + b2 -> global, staged in usp
    {
        u64 aO[4];
        #pragma unroll
        for (int p = 0; p < 4; p++) aO[p] = 0ULL;
        const float2* wp = g_W2T2 + c;
        for (int kp = 0; kp < 128; kp++) {
            float2 w2 = wp[(size_t)kp * Dd];
            u64 d0 = dup2(w2.x), d1 = dup2(w2.y);
            int k = 2 * kp;
            #pragma unroll
            for (int p = 0; p < 4; p++) {
                ulonglong2 x2 = *(const ulonglong2*)&fsp[p][k];
                fma2(aO[p], x2.x, d0); fma2(aO[p], x2.y, d1);
            }
        }
        float b2c = b2[c];
        __syncthreads();       // fsp reads done before Phase G rewrites fsp
        #pragma unroll
        for (int p = 0; p < 4; p++) {
            float2 o2 = unpk(aO[p]);
            float snlo = hnlo[p] + o2.x + b2c;
            float snhi = hnhi[p] + o2.y + b2c;
            int rlo = i0 + 2 * p;
            g_slots[((size_t)b * Ss + rlo) * Dd + c] = snlo;
            if (2 * p + 1 < RS) g_slots[((size_t)b * Ss + rlo + 1) * Dd + c] = snhi;
            usp[p][c] = make_float2(snlo, snhi);
        }
    }
    __syncthreads();

    // Phase G: next-iter Q = LN(slots_new; g_sl) @ WqT + bq
    {
        int p = w >> 1, e = w & 1;
        float v[8]; float s = 0.f;
        #pragma unroll
        for (int u = 0; u < 8; u++) {
            v[u] = ((const float*)usp)[((size_t)p * Dd + l + 32 * u) * 2 + e];
            s += v[u];
        }
        s = warp_sum(s);
        float m = s * (1.0f / Dd);
        float vs = 0.f;
        #pragma unroll
        for (int u = 0; u < 8; u++) { v[u] -= m; vs += v[u] * v[u]; }
        vs = warp_sum(vs);
        float iv = rsqrtf(vs * (1.0f / Dd) + LN_EPS);
        #pragma unroll
        for (int u = 0; u < 8; u++) {
            int k = l + 32 * u;
            ((float*)fsp)[((size_t)p * Dd + k) * 2 + e] = v[u] * iv * g_sl[k] + be_sl[k];
        }
    }
    __syncthreads();
    {
        u64 aQ[4];
        #pragma unroll
        for (int p = 0; p < 4; p++) aQ[p] = 0ULL;
        const float2* wp = g_WqT2 + c;
        for (int kp = 0; kp < 128; kp++) {
            float2 w2 = wp[(size_t)kp * Dd];
            u64 d0 = dup2(w2.x), d1 = dup2(w2.y);
            int k = 2 * kp;
            #pragma unroll
            for (int p = 0; p < 4; p++) {
                ulonglong2 x2 = *(const ulonglong2*)&fsp[p][k];
                fma2(aQ[p], x2.x, d0); fma2(aQ[p], x2.y, d1);
            }
        }
        float bqc = bq[c];
        #pragma unroll
        for (int p = 0; p < 4; p++) {
            float2 q2 = unpk(aQ[p]);
            int rlo = i0 + 2 * p;
            g_Q[((size_t)b * Ss + rlo) * Dd + c] = q2.x + bqc;
            if (2 * p + 1 < RS) g_Q[((size_t)b * Ss + rlo + 1) * Dd + c] = q2.y + bqc;
        }
    }
}

// ---------------- output slots ------------------------------------------------
__global__ void out_slots_kernel(float* __restrict__ out) {
    int idx = blockIdx.x * blockDim.x + threadIdx.x;
    int d = idx & (Dd - 1);
    int rest = idx / Dd;
    int s = rest % NA;
    int b = rest / NA;
    out[idx] = g_slots[((size_t)b * Ss + s) * Dd + d];
}

// ---------------- launch ------------------------------------------------------
extern "C" void kernel_launch(void* const* d_in, const int* in_sizes, int n_in,
                              void* d_out, int out_size) {
    const float* inputs = (const float*)d_in[0];
    const float* noise  = (const float*)d_in[1];
    const float* mu     = (const float*)d_in[2];
    const float* sigma  = (const float*)d_in[3];
    const float* Wq     = (const float*)d_in[4];
    const float* bq     = (const float*)d_in[5];
    const float* Wk     = (const float*)d_in[6];
    const float* bk     = (const float*)d_in[7];
    const float* Wv     = (const float*)d_in[8];
    const float* bv     = (const float*)d_in[9];
    const float* W1     = (const float*)d_in[10];
    const float* b1     = (const float*)d_in[11];
    const float* W2     = (const float*)d_in[12];
    const float* b2     = (const float*)d_in[13];
    const float* W_ih   = (const float*)d_in[14];
    const float* b_ih   = (const float*)d_in[15];
    const float* W_hh   = (const float*)d_in[16];
    const float* b_hh   = (const float*)d_in[17];
    const float* gin    = (const float*)d_in[18];
    const float* bein   = (const float*)d_in[19];
    const float* gsl    = (const float*)d_in[20];
    const float* besl   = (const float*)d_in[21];
    const float* gff    = (const float*)d_in[22];
    const float* beff   = (const float*)d_in[23];

    float* out = (float*)d_out;
    float* out_attn = out + (size_t)Bz * NA * Dd;

    transpose2_all_kernel<<<352, dim3(32, 8)>>>(Wq, Wk, Wv, W1, W2, W_ih, W_hh);
    init_slots_kernel<<<(Bz * Ss * Dd) / 256, 256>>>(noise, mu, sigma);
    kv_all_kernel<<<(Bz * NFr * Nn) / RLN, 256>>>(inputs, gin, bein, bk, bv);
    q_kernel<<<(Bz * Ss) / RQ, 256>>>(gsl, besl, bq);

    for (int f = 0; f < NFr; f++) {
        for (int it = 0; it < 3; it++) {
            dots_softmax_kernel<<<Bz * (Nn / 32), 256>>>(f, (it == 2) ? 1 : 0, out_attn);
            slot_update_kernel<<<Bz * 3, 256>>>(f, b_ih, b_hh, gff, beff,
                                                b1, b2, gsl, besl, bq);
        }
    }

    out_slots_kernel<<<(Bz * NA * Dd) / 256, 256>>>(out);
}

// round 5
// speedup vs baseline: 23.5989x; 1.0237x over previous
#include <cuda_runtime.h>
#include <math.h>

#define Bz 32
#define NFr 16
#define Dd 256
#define Ss 21
#define Nn 192
#define NA 20
#define EPSs 1e-8f
#define LN_EPS 1e-5f
#define RLN 24   // rows per block in kv_all (12 pairs)
#define RQ 8
#define RS 7     // slot rows per block (4 pairs, last hi = dup)

typedef unsigned long long u64;

// ---------------- packed f32x2 helpers ---------------------------------------
__device__ __forceinline__ void fma2(u64& d, u64 a, u64 b) {
    asm("fma.rn.f32x2 %0, %1, %2, %0;" : "+l"(d) : "l"(a), "l"(b));
}
__device__ __forceinline__ u64 dup2(float v) {
    u64 r; asm("mov.b64 %0, {%1, %1};" : "=l"(r) : "f"(v)); return r;
}
__device__ __forceinline__ float2 unpk(u64 v) {
    float lo, hi; asm("mov.b64 {%0, %1}, %2;" : "=f"(lo), "=f"(hi) : "l"(v));
    return make_float2(lo, hi);
}

// ---------------- scratch ----------------------------------------------------
__device__ float g_K[(size_t)Bz * NFr * Nn * Dd];   // [b][f][n][d]
__device__ float g_V[(size_t)Bz * NFr * Nn * Dd];
__device__ float g_slots[Bz * Ss * Dd];
__device__ float g_Q[Bz * Ss * Dd];
__device__ float g_At[Bz * Nn * Ss];                // attn_ori^T: [b][j][i]
__device__ unsigned g_dots_done[Bz];
__device__ unsigned g_slot_done[Bz];
// pair-interleaved transposed weights: WT2[kp][c] = (W[c][2kp], W[c][2kp+1])
__device__ float2 g_WqT2[128 * Dd];
__device__ float2 g_WkT2[128 * Dd];
__device__ float2 g_WvT2[128 * Dd];
__device__ float2 g_W1T2[128 * Dd];
__device__ float2 g_W2T2[128 * Dd];
__device__ float2 g_WihT2[128 * 3 * Dd];
__device__ float2 g_WhhT2[128 * 3 * Dd];

// ---------------- sync helpers ------------------------------------------------
__device__ __forceinline__ void wait_ge(unsigned* p, unsigned tgt) {
    if (threadIdx.x == 0) {
        unsigned v;
        do {
            asm volatile("ld.acquire.gpu.global.u32 %0, [%1];"
                         : "=r"(v) : "l"(p) : "memory");
        } while (v < tgt);
    }
    __syncthreads();
}
__device__ __forceinline__ void signal(unsigned* p) {
    __syncthreads();
    if (threadIdx.x == 0) { __threadfence(); atomicAdd(p, 1u); }
}

// ---------------- fused f2-transpose of all 7 weight matrices ----------------
__global__ void transpose2_all_kernel(const float* __restrict__ Wq, const float* __restrict__ Wk,
                                      const float* __restrict__ Wv, const float* __restrict__ W1,
                                      const float* __restrict__ W2, const float* __restrict__ Wih,
                                      const float* __restrict__ Whh) {
    __shared__ float2 tile[32][33];
    int bid = blockIdx.x;
    const float2* src; float2* dst; int R; int tloc;
    if (bid < 160) {
        int m = bid >> 5; tloc = bid & 31; R = 256;
        switch (m) {
            case 0: src = (const float2*)Wq; dst = g_WqT2; break;
            case 1: src = (const float2*)Wk; dst = g_WkT2; break;
            case 2: src = (const float2*)Wv; dst = g_WvT2; break;
            case 3: src = (const float2*)W1; dst = g_W1T2; break;
            default: src = (const float2*)W2; dst = g_W2T2; break;
        }
    } else {
        int m = (bid - 160) / 96; tloc = (bid - 160) % 96; R = 768;
        src = (const float2*)(m == 0 ? Wih : Whh);
        dst = (m == 0 ? g_WihT2 : g_WhhT2);
    }
    int bx = (tloc & 3) * 32;
    int by = (tloc >> 2) * 32;
    int tx = threadIdx.x, ty = threadIdx.y;
    #pragma unroll
    for (int i = 0; i < 32; i += 8)
        tile[ty + i][tx] = src[(size_t)(by + ty + i) * 128 + bx + tx];
    __syncthreads();
    #pragma unroll
    for (int i = 0; i < 32; i += 8)
        dst[(size_t)(bx + ty + i) * R + by + tx] = tile[tx][ty + i];
}

// ---------------- init slots --------------------------------------------------
__global__ void init_slots_kernel(const float* __restrict__ noise,
                                  const float* __restrict__ mu,
                                  const float* __restrict__ sigma) {
    int idx = blockIdx.x * blockDim.x + threadIdx.x;
    int d = idx & (Dd - 1);
    g_slots[idx] = mu[d] + sigma[d] * noise[idx];
}

// ---------------- warp helpers ------------------------------------------------
__device__ __forceinline__ float warp_sum(float v) {
    #pragma unroll
    for (int o = 16; o > 0; o >>= 1) v += __shfl_xor_sync(0xffffffffu, v, o);
    return v;
}
__device__ __forceinline__ float warp_max(float v) {
    #pragma unroll
    for (int o = 16; o > 0; o >>= 1) v = fmaxf(v, __shfl_xor_sync(0xffffffffu, v, o));
    return v;
}

// ------- LN(all frames) -> K,V.  grid = B*NF*N/RLN = 4096 --------------------
__global__ __launch_bounds__(256)
void kv_all_kernel(const float* __restrict__ inputs,
                   const float* __restrict__ gam, const float* __restrict__ bet,
                   const float* __restrict__ bk, const float* __restrict__ bv) {
    __shared__ float2 xs2[RLN / 2][Dd];
    int row0 = blockIdx.x * RLN;
    int t = threadIdx.x, w = t >> 5, l = t & 31;

    for (int rr = w; rr < RLN; rr += 8) {
        int row = row0 + rr;
        const float* src = inputs + (size_t)row * Dd;
        float v[8]; float s = 0.f;
        #pragma unroll
        for (int u = 0; u < 8; u++) { v[u] = src[l + 32 * u]; s += v[u]; }
        s = warp_sum(s);
        float m = s * (1.0f / Dd);
        float vs = 0.f;
        #pragma unroll
        for (int u = 0; u < 8; u++) { v[u] -= m; vs += v[u] * v[u]; }
        vs = warp_sum(vs);
        float inv = rsqrtf(vs * (1.0f / Dd) + LN_EPS);
        int p = rr >> 1, e = rr & 1;
        #pragma unroll
        for (int u = 0; u < 8; u++) {
            int k = l + 32 * u;
            ((float*)xs2)[((size_t)p * Dd + k) * 2 + e] = v[u] * inv * gam[k] + bet[k];
        }
    }
    __syncthreads();

    int c = t;
    u64 aK[RLN / 2], aV[RLN / 2];
    #pragma unroll
    for (int p = 0; p < RLN / 2; p++) { aK[p] = 0ULL; aV[p] = 0ULL; }
    const float2* wk2 = g_WkT2 + c;
    const float2* wv2 = g_WvT2 + c;
    for (int kp = 0; kp < 128; kp++) {
        float2 wk = wk2[(size_t)kp * Dd];
        float2 wv = wv2[(size_t)kp * Dd];
        u64 dk0 = dup2(wk.x), dk1 = dup2(wk.y);
        u64 dv0 = dup2(wv.x), dv1 = dup2(wv.y);
        int k = 2 * kp;
        #pragma unroll
        for (int p = 0; p < RLN / 2; p++) {
            ulonglong2 x2 = *(const ulonglong2*)&xs2[p][k];
            fma2(aK[p], x2.x, dk0); fma2(aK[p], x2.y, dk1);
            fma2(aV[p], x2.x, dv0); fma2(aV[p], x2.y, dv1);
        }
    }
    float bkc = bk[c], bvc = bv[c];
    #pragma unroll
    for (int p = 0; p < RLN / 2; p++) {
        float2 k2 = unpk(aK[p]);
        float2 v2 = unpk(aV[p]);
        g_K[(size_t)(row0 + 2 * p) * Dd + c]     = k2.x + bkc;
        g_K[(size_t)(row0 + 2 * p + 1) * Dd + c] = k2.y + bkc;
        g_V[(size_t)(row0 + 2 * p) * Dd + c]     = v2.x + bvc;
        g_V[(size_t)(row0 + 2 * p + 1) * Dd + c] = v2.y + bvc;
    }
}

// ---------------- initial Q = LN(slots)@WqT + bq; also zeroes counters --------
__global__ __launch_bounds__(256)
void q_kernel(const float* __restrict__ gam, const float* __restrict__ bet,
              const float* __restrict__ bq) {
    __shared__ float xs[RQ][Dd];
    int row0 = blockIdx.x * RQ;
    int t = threadIdx.x, w = t >> 5, l = t & 31;
    if (blockIdx.x == 0 && t < Bz) { g_dots_done[t] = 0u; g_slot_done[t] = 0u; }
    if (w < RQ) {
        int row = row0 + w;
        const float* src = g_slots + (size_t)row * Dd;
        float v[8]; float s = 0.f;
        #pragma unroll
        for (int u = 0; u < 8; u++) { v[u] = src[l + 32 * u]; s += v[u]; }
        s = warp_sum(s);
        float m = s * (1.0f / Dd);
        float vs = 0.f;
        #pragma unroll
        for (int u = 0; u < 8; u++) { v[u] -= m; vs += v[u] * v[u]; }
        vs = warp_sum(vs);
        float inv = rsqrtf(vs * (1.0f / Dd) + LN_EPS);
        #pragma unroll
        for (int u = 0; u < 8; u++) {
            int k = l + 32 * u;
            xs[w][k] = v[u] * inv * gam[k] + bet[k];
        }
    }
    __syncthreads();
    int c = t;
    float acc[RQ];
    float bqc = bq[c];
    #pragma unroll
    for (int r = 0; r < RQ; r++) acc[r] = bqc;
    const float2* wp = g_WqT2 + c;
    for (int kp = 0; kp < 128; kp++) {
        float2 w2 = wp[(size_t)kp * Dd];
        int k = 2 * kp;
        #pragma unroll
        for (int r = 0; r < RQ; r++) {
            float2 x2 = *(const float2*)&xs[r][k];
            acc[r] = fmaf(x2.x, w2.x, acc[r]);
            acc[r] = fmaf(x2.y, w2.y, acc[r]);
        }
    }
    #pragma unroll
    for (int r = 0; r < RQ; r++) g_Q[(size_t)(row0 + r) * Dd + c] = acc[r];
}

// ---------------- persistent kernel: all 48 iterations ------------------------
// grid = Bz * 9. roles 0-5: dots tiles (32 j each). roles 6-8: slot updates (7 rows).
union SMem {
    struct { float Ks[32][68]; float Qs[Ss][64]; float ds[32][24]; } d;
    struct { float2 asp[4][Nn]; float2 usp[4][Dd]; float2 hsp[4][Dd];
             float2 fsp[4][Dd]; float inv_[8]; } s;
};

__global__ __launch_bounds__(256, 2)
void persist_kernel(float* __restrict__ out_attn,
                    const float* __restrict__ b_ih, const float* __restrict__ b_hh,
                    const float* __restrict__ g_ff, const float* __restrict__ be_ff,
                    const float* __restrict__ b1, const float* __restrict__ b2,
                    const float* __restrict__ g_sl, const float* __restrict__ be_sl,
                    const float* __restrict__ bq) {
    __shared__ SMem sm;
    int b = blockIdx.x / 9;
    int role = blockIdx.x % 9;
    int t = threadIdx.x, w = t >> 5, l = t & 31;

    if (role < 6) {
        // ================= DOTS block =================
        int j0 = role * 32;
        int jj = l;
        int i0 = w, i1 = w + 8, i2 = w + 16;
        bool has2 = (i2 < Ss);
        for (int iter = 0; iter < NFr * 3; iter++) {
            int f = iter / 3, it = iter - 3 * f;
            wait_ge(&g_slot_done[b], 3u * iter);      // Q of this iter ready
            u64 A0 = 0ULL, A1 = 0ULL, A2 = 0ULL;
            const float* Kbase = g_K + (((size_t)b * NFr + f) * Nn) * Dd;
            for (int k0 = 0; k0 < Dd; k0 += 64) {
                for (int idx = t; idx < 32 * 16; idx += 256) {
                    int r = idx >> 4, kk4 = (idx & 15) * 4;
                    *(float4*)&sm.d.Ks[r][kk4] =
                        *(const float4*)&Kbase[(size_t)(j0 + r) * Dd + k0 + kk4];
                }
                for (int idx = t; idx < Ss * 16; idx += 256) {
                    int r = idx >> 4, kk4 = (idx & 15) * 4;
                    *(float4*)&sm.d.Qs[r][kk4] =
                        __ldcg((const float4*)&g_Q[((size_t)b * Ss + r) * Dd + k0 + kk4]);
                }
                __syncthreads();
                #pragma unroll
                for (int kk = 0; kk < 64; kk += 4) {
                    ulonglong2 kp = *(const ulonglong2*)&sm.d.Ks[jj][kk];
                    ulonglong2 q0 = *(const ulonglong2*)&sm.d.Qs[i0][kk];
                    ulonglong2 q1 = *(const ulonglong2*)&sm.d.Qs[i1][kk];
                    fma2(A0, kp.x, q0.x); fma2(A0, kp.y, q0.y);
                    fma2(A1, kp.x, q1.x); fma2(A1, kp.y, q1.y);
                    if (has2) {
                        ulonglong2 q2 = *(const ulonglong2*)&sm.d.Qs[i2][kk];
                        fma2(A2, kp.x, q2.x); fma2(A2, kp.y, q2.y);
                    }
                }
                __syncthreads();
            }
            float2 s0 = unpk(A0), s1 = unpk(A1);
            sm.d.ds[jj][i0] = (s0.x + s0.y) * 0.0625f;
            sm.d.ds[jj][i1] = (s1.x + s1.y) * 0.0625f;
            if (has2) { float2 s2 = unpk(A2); sm.d.ds[jj][i2] = (s2.x + s2.y) * 0.0625f; }
            __syncthreads();
            for (int q = w; q < 32; q += 8) {
                float v = (l < Ss) ? sm.d.ds[q][l] : -3.4e38f;
                float mx = warp_max(v);
                float e = (l < Ss) ? expf(v - mx) : 0.f;
                float smv = warp_sum(e);
                if (l < Ss) {
                    float a = e / smv + EPSs;
                    g_At[((size_t)b * Nn + j0 + q) * Ss + l] = a;
                    if (it == 2)
                        out_attn[(((size_t)b * NFr + f) * Ss + l) * Nn + j0 + q] = a;
                }
            }
            __syncthreads();   // ds reads done before next iter reuses smem
            signal(&g_dots_done[b]);
        }
    } else {
        // ================= SLOT block =================
        int i0 = (role - 6) * RS;
        int c = t;
        for (int iter = 0; iter < NFr * 3; iter++) {
            int f = iter / 3;
            wait_ge(&g_dots_done[b], 6u * (iter + 1));   // attn of this iter ready

            // Phase A: stage attn (L2 reads) + row sums
            for (int idx = t; idx < 8 * Nn; idx += 256) {
                int lr = idx & 7, j = idx >> 3;
                int row = (lr < 7) ? lr : 6;
                ((float*)sm.s.asp)[((size_t)(lr >> 1) * Nn + j) * 2 + (lr & 1)] =
                    __ldcg(&g_At[((size_t)b * Nn + j) * Ss + i0 + row]);
            }
            __syncthreads();
            {
                int p = w >> 1, e = w & 1;
                float s = 0.f;
                #pragma unroll
                for (int u = 0; u < Nn / 32; u++)
                    s += ((const float*)sm.s.asp)[((size_t)p * Nn + l + 32 * u) * 2 + e];
                s = warp_sum(s);
                if (l == 0) sm.s.inv_[w] = 1.0f / s;
            }
            float h0lo[4], h0hi[4];
            #pragma unroll
            for (int p = 0; p < 4; p++) {
                int rlo = 2 * p, rhi = (2 * p + 1 < RS) ? 2 * p + 1 : RS - 1;
                h0lo[p] = g_slots[((size_t)b * Ss + i0 + rlo) * Dd + c];
                h0hi[p] = g_slots[((size_t)b * Ss + i0 + rhi) * Dd + c];
            }
            __syncthreads();

            // Phase B: updates = (A/rowsum) @ V
            u64 accU[4];
            #pragma unroll
            for (int p = 0; p < 4; p++) accU[p] = 0ULL;
            const float* vp = g_V + (((size_t)b * NFr + f) * Nn) * Dd + c;
            for (int j = 0; j < Nn; j += 2) {
                u64 vd0 = dup2(vp[(size_t)j * Dd]);
                u64 vd1 = dup2(vp[(size_t)(j + 1) * Dd]);
                #pragma unroll
                for (int p = 0; p < 4; p++) {
                    ulonglong2 a2 = *(const ulonglong2*)&sm.s.asp[p][j];
                    fma2(accU[p], a2.x, vd0);
                    fma2(accU[p], a2.y, vd1);
                }
            }
            #pragma unroll
            for (int p = 0; p < 4; p++) {
                float2 u2 = unpk(accU[p]);
                sm.s.usp[p][c] = make_float2(u2.x * sm.s.inv_[2 * p],
                                             u2.y * sm.s.inv_[2 * p + 1]);
                sm.s.hsp[p][c] = make_float2(h0lo[p], h0hi[p]);
            }
            __syncthreads();

            // Phase C: GRU gates
            u64 a_ir[4], a_iz[4], a_in[4], a_hr[4], a_hz[4], a_hn[4];
            #pragma unroll
            for (int p = 0; p < 4; p++) {
                a_ir[p] = 0ULL; a_iz[p] = 0ULL; a_in[p] = 0ULL;
                a_hr[p] = 0ULL; a_hz[p] = 0ULL; a_hn[p] = 0ULL;
            }
            const float2* wip2 = g_WihT2 + c;
            const float2* whp2 = g_WhhT2 + c;
            for (int kp = 0; kp < 128; kp++) {
                float2 wr_ = wip2[(size_t)kp * (3 * Dd)];
                float2 wz_ = wip2[(size_t)kp * (3 * Dd) + Dd];
                float2 wn_ = wip2[(size_t)kp * (3 * Dd) + 2 * Dd];
                float2 vr_ = whp2[(size_t)kp * (3 * Dd)];
                float2 vz_ = whp2[(size_t)kp * (3 * Dd) + Dd];
                float2 vn_ = whp2[(size_t)kp * (3 * Dd) + 2 * Dd];
                u64 dir0 = dup2(wr_.x), dir1 = dup2(wr_.y);
                u64 diz0 = dup2(wz_.x), diz1 = dup2(wz_.y);
                u64 din0 = dup2(wn_.x), din1 = dup2(wn_.y);
                u64 dhr0 = dup2(vr_.x), dhr1 = dup2(vr_.y);
                u64 dhz0 = dup2(vz_.x), dhz1 = dup2(vz_.y);
                u64 dhn0 = dup2(vn_.x), dhn1 = dup2(vn_.y);
                int k = 2 * kp;
                #pragma unroll
                for (int p = 0; p < 4; p++) {
                    ulonglong2 u2 = *(const ulonglong2*)&sm.s.usp[p][k];
                    ulonglong2 h2 = *(const ulonglong2*)&sm.s.hsp[p][k];
                    fma2(a_ir[p], u2.x, dir0); fma2(a_ir[p], u2.y, dir1);
                    fma2(a_iz[p], u2.x, diz0); fma2(a_iz[p], u2.y, diz1);
                    fma2(a_in[p], u2.x, din0); fma2(a_in[p], u2.y, din1);
                    fma2(a_hr[p], h2.x, dhr0); fma2(a_hr[p], h2.y, dhr1);
                    fma2(a_hz[p], h2.x, dhz0); fma2(a_hz[p], h2.y, dhz1);
                    fma2(a_hn[p], h2.x, dhn0); fma2(a_hn[p], h2.y, dhn1);
                }
            }
            float bir = b_ih[c], biz = b_ih[Dd + c], bin = b_ih[2 * Dd + c];
            float bhr = b_hh[c], bhz = b_hh[Dd + c], bhn = b_hh[2 * Dd + c];
            float hnlo[4], hnhi[4];
            #pragma unroll
            for (int p = 0; p < 4; p++) {
                float2 ir2 = unpk(a_ir[p]), iz2 = unpk(a_iz[p]), in2 = unpk(a_in[p]);
                float2 hr2 = unpk(a_hr[p]), hz2 = unpk(a_hz[p]), hn2 = unpk(a_hn[p]);
                {
                    float rg = 1.f / (1.f + expf(-(ir2.x + bir + hr2.x + bhr)));
                    float zg = 1.f / (1.f + expf(-(iz2.x + biz + hz2.x + bhz)));
                    float ng = tanhf(in2.x + bin + rg * (hn2.x + bhn));
                    hnlo[p] = (1.f - zg) * ng + zg * h0lo[p];
                }
                {
                    float rg = 1.f / (1.f + expf(-(ir2.y + bir + hr2.y + bhr)));
                    float zg = 1.f / (1.f + expf(-(iz2.y + biz + hz2.y + bhz)));
                    float ng = tanhf(in2.y + bin + rg * (hn2.y + bhn));
                    hnhi[p] = (1.f - zg) * ng + zg * h0hi[p];
                }
            }
            __syncthreads();
            #pragma unroll
            for (int p = 0; p < 4; p++) sm.s.usp[p][c] = make_float2(hnlo[p], hnhi[p]);
            __syncthreads();

            // Phase D: LN(hnew; g_ff) -> hsp
            {
                int p = w >> 1, e = w & 1;
                float v[8]; float s = 0.f;
                #pragma unroll
                for (int u = 0; u < 8; u++) {
                    v[u] = ((const float*)sm.s.usp)[((size_t)p * Dd + l + 32 * u) * 2 + e];
                    s += v[u];
                }
                s = warp_sum(s);
                float m = s * (1.0f / Dd);
                float vs = 0.f;
                #pragma unroll
                for (int u = 0; u < 8; u++) { v[u] -= m; vs += v[u] * v[u]; }
                vs = warp_sum(vs);
                float iv = rsqrtf(vs * (1.0f / Dd) + LN_EPS);
                #pragma unroll
                for (int u = 0; u < 8; u++) {
                    int k = l + 32 * u;
                    ((float*)sm.s.hsp)[((size_t)p * Dd + k) * 2 + e] =
                        v[u] * iv * g_ff[k] + be_ff[k];
                }
            }
            __syncthreads();

            // Phase E: FF = relu(LN @ W1T + b1) -> fsp
            {
                u64 aF[4];
                #pragma unroll
                for (int p = 0; p < 4; p++) aF[p] = 0ULL;
                const float2* wp = g_W1T2 + c;
                for (int kp = 0; kp < 128; kp++) {
                    float2 w2 = wp[(size_t)kp * Dd];
                    u64 d0 = dup2(w2.x), d1 = dup2(w2.y);
                    int k = 2 * kp;
                    #pragma unroll
                    for (int p = 0; p < 4; p++) {
                        ulonglong2 x2 = *(const ulonglong2*)&sm.s.hsp[p][k];
                        fma2(aF[p], x2.x, d0); fma2(aF[p], x2.y, d1);
                    }
                }
                float b1c = b1[c];
                #pragma unroll
                for (int p = 0; p < 4; p++) {
                    float2 f2 = unpk(aF[p]);
                    sm.s.fsp[p][c] = make_float2(fmaxf(f2.x + b1c, 0.f),
                                                 fmaxf(f2.y + b1c, 0.f));
                }
            }
            __syncthreads();

            // Phase F: slots_new = hnew + fsp @ W2T + b2
            {
                u64 aO[4];
                #pragma unroll
                for (int p = 0; p < 4; p++) aO[p] = 0ULL;
                const float2* wp = g_W2T2 + c;
                for (int kp = 0; kp < 128; kp++) {
                    float2 w2 = wp[(size_t)kp * Dd];
                    u64 d0 = dup2(w2.x), d1 = dup2(w2.y);
                    int k = 2 * kp;
                    #pragma unroll
                    for (int p = 0; p < 4; p++) {
                        ulonglong2 x2 = *(const ulonglong2*)&sm.s.fsp[p][k];
                        fma2(aO[p], x2.x, d0); fma2(aO[p], x2.y, d1);
                    }
                }
                float b2c = b2[c];
                __syncthreads();
                #pragma unroll
                for (int p = 0; p < 4; p++) {
                    float2 o2 = unpk(aO[p]);
                    float snlo = hnlo[p] + o2.x + b2c;
                    float snhi = hnhi[p] + o2.y + b2c;
                    int rlo = i0 + 2 * p;
                    g_slots[((size_t)b * Ss + rlo) * Dd + c] = snlo;
                    if (2 * p + 1 < RS) g_slots[((size_t)b * Ss + rlo + 1) * Dd + c] = snhi;
                    sm.s.usp[p][c] = make_float2(snlo, snhi);
                }
            }
            __syncthreads();

            // Phase G: next-iter Q = LN(slots_new; g_sl) @ WqT + bq
            {
                int p = w >> 1, e = w & 1;
                float v[8]; float s = 0.f;
                #pragma unroll
                for (int u = 0; u < 8; u++) {
                    v[u] = ((const float*)sm.s.usp)[((size_t)p * Dd + l + 32 * u) * 2 + e];
                    s += v[u];
                }
                s = warp_sum(s);
                float m = s * (1.0f / Dd);
                float vs = 0.f;
                #pragma unroll
                for (int u = 0; u < 8; u++) { v[u] -= m; vs += v[u] * v[u]; }
                vs = warp_sum(vs);
                float iv = rsqrtf(vs * (1.0f / Dd) + LN_EPS);
                #pragma unroll
                for (int u = 0; u < 8; u++) {
                    int k = l + 32 * u;
                    ((float*)sm.s.fsp)[((size_t)p * Dd + k) * 2 + e] =
                        v[u] * iv * g_sl[k] + be_sl[k];
                }
            }
            __syncthreads();
            {
                u64 aQ[4];
                #pragma unroll
                for (int p = 0; p < 4; p++) aQ[p] = 0ULL;
                const float2* wp = g_WqT2 + c;
                for (int kp = 0; kp < 128; kp++) {
                    float2 w2 = wp[(size_t)kp * Dd];
                    u64 d0 = dup2(w2.x), d1 = dup2(w2.y);
                    int k = 2 * kp;
                    #pragma unroll
                    for (int p = 0; p < 4; p++) {
                        ulonglong2 x2 = *(const ulonglong2*)&sm.s.fsp[p][k];
                        fma2(aQ[p], x2.x, d0); fma2(aQ[p], x2.y, d1);
                    }
                }
                float bqc = bq[c];
                #pragma unroll
                for (int p = 0; p < 4; p++) {
                    float2 q2 = unpk(aQ[p]);
                    int rlo = i0 + 2 * p;
                    g_Q[((size_t)b * Ss + rlo) * Dd + c] = q2.x + bqc;
                    if (2 * p + 1 < RS) g_Q[((size_t)b * Ss + rlo + 1) * Dd + c] = q2.y + bqc;
                }
            }
            signal(&g_slot_done[b]);
        }
    }
}

// ---------------- output slots ------------------------------------------------
__global__ void out_slots_kernel(float* __restrict__ out) {
    int idx = blockIdx.x * blockDim.x + threadIdx.x;
    int d = idx & (Dd - 1);
    int rest = idx / Dd;
    int s = rest % NA;
    int b = rest / NA;
    out[idx] = g_slots[((size_t)b * Ss + s) * Dd + d];
}

// ---------------- launch ------------------------------------------------------
extern "C" void kernel_launch(void* const* d_in, const int* in_sizes, int n_in,
                              void* d_out, int out_size) {
    const float* inputs = (const float*)d_in[0];
    const float* noise  = (const float*)d_in[1];
    const float* mu     = (const float*)d_in[2];
    const float* sigma  = (const float*)d_in[3];
    const float* Wq     = (const float*)d_in[4];
    const float* bq     = (const float*)d_in[5];
    const float* Wk     = (const float*)d_in[6];
    const float* bk     = (const float*)d_in[7];
    const float* Wv     = (const float*)d_in[8];
    const float* bv     = (const float*)d_in[9];
    const float* W1     = (const float*)d_in[10];
    const float* b1     = (const float*)d_in[11];
    const float* W2     = (const float*)d_in[12];
    const float* b2     = (const float*)d_in[13];
    const float* W_ih   = (const float*)d_in[14];
    const float* b_ih   = (const float*)d_in[15];
    const float* W_hh   = (const float*)d_in[16];
    const float* b_hh   = (const float*)d_in[17];
    const float* gin    = (const float*)d_in[18];
    const float* bein   = (const float*)d_in[19];
    const float* gsl    = (const float*)d_in[20];
    const float* besl   = (const float*)d_in[21];
    const float* gff    = (const float*)d_in[22];
    const float* beff   = (const float*)d_in[23];

    float* out = (float*)d_out;
    float* out_attn = out + (size_t)Bz * NA * Dd;

    transpose2_all_kernel<<<352, dim3(32, 8)>>>(Wq, Wk, Wv, W1, W2, W_ih, W_hh);
    init_slots_kernel<<<(Bz * Ss * Dd) / 256, 256>>>(noise, mu, sigma);
    kv_all_kernel<<<(Bz * NFr * Nn) / RLN, 256>>>(inputs, gin, bein, bk, bv);
    q_kernel<<<(Bz * Ss) / RQ, 256>>>(gsl, besl, bq);
    persist_kernel<<<Bz * 9, 256>>>(out_attn, b_ih, b_hh, gff, beff,
                                    b1, b2, gsl, besl, bq);
    out_slots_kernel<<<(Bz * NA * Dd) / 256, 256>>>(out);
}